// round 4
// baseline (speedup 1.0000x reference)
#include <cuda_runtime.h>
#include <cstdint>

// ---------------- scratch (__device__ globals; no allocs allowed) ------------
__device__ int   g_hq8[1048576];     // hidden quantized int8, packed 4/int32
__device__ int   g_r8 [1048576];     // residual quantized int8, packed
__device__ int   g_wq8[262144];
__device__ int   g_wk8[262144];
__device__ int   g_wv8[262144];
__device__ float g_Q[4194304];       // [B*H, S, 64]
__device__ float g_K[4194304];
__device__ float g_V[4194304];
__device__ unsigned int g_absmax[4]; // 0:hidden 1:Wq 2:Wk 3:Wv

// ---------------- absmax / packing ------------------------------------------
__global__ void init_k() {
    if (threadIdx.x < 4) g_absmax[threadIdx.x] = 0u;
}

__global__ void absmax4_k(const float4* __restrict__ x, int n4, int slot) {
    float m = 0.f;
    for (int i = blockIdx.x * blockDim.x + threadIdx.x; i < n4; i += gridDim.x * blockDim.x) {
        float4 v = x[i];
        m = fmaxf(m, fmaxf(fmaxf(fabsf(v.x), fabsf(v.y)), fmaxf(fabsf(v.z), fabsf(v.w))));
    }
#pragma unroll
    for (int o = 16; o > 0; o >>= 1) m = fmaxf(m, __shfl_xor_sync(0xffffffffu, m, o));
    if ((threadIdx.x & 31) == 0) atomicMax(&g_absmax[slot], __float_as_uint(m));
}

// all 3 weight absmax in one launch (blockIdx.z selects)
__global__ void absmax_w_k(const float4* __restrict__ wq, const float4* __restrict__ wk,
                           const float4* __restrict__ wv, int n4) {
    int z = blockIdx.z;
    const float4* x = (z == 0) ? wq : (z == 1) ? wk : wv;
    float m = 0.f;
    for (int i = blockIdx.x * blockDim.x + threadIdx.x; i < n4; i += gridDim.x * blockDim.x) {
        float4 v = x[i];
        m = fmaxf(m, fmaxf(fmaxf(fabsf(v.x), fabsf(v.y)), fmaxf(fabsf(v.z), fabsf(v.w))));
    }
#pragma unroll
    for (int o = 16; o > 0; o >>= 1) m = fmaxf(m, __shfl_xor_sync(0xffffffffu, m, o));
    if ((threadIdx.x & 31) == 0) atomicMax(&g_absmax[z + 1], __float_as_uint(m));
}

__device__ __forceinline__ int pack4i(float a, float b, float c, float d) {
    int ia = (int)a, ib = (int)b, ic = (int)c, id = (int)d;
    return (ia & 0xFF) | ((ib & 0xFF) << 8) | ((ic & 0xFF) << 16) | ((id & 0xFF) << 24);
}

// hidden -> int8 (scale s = max/127) + residual int8 (scale s/254). Exact split.
__global__ void pack_act_k(const float4* __restrict__ x, int* __restrict__ q8,
                           int* __restrict__ r8, int n4) {
    float s  = fmaxf(__uint_as_float(g_absmax[0]), 1e-8f) / 127.0f;
    float s2 = s / 254.0f;
    for (int i = blockIdx.x * blockDim.x + threadIdx.x; i < n4; i += gridDim.x * blockDim.x) {
        float4 v = x[i];
        float qa = fminf(fmaxf(rintf(v.x / s), -127.f), 127.f);
        float qb = fminf(fmaxf(rintf(v.y / s), -127.f), 127.f);
        float qc = fminf(fmaxf(rintf(v.z / s), -127.f), 127.f);
        float qd = fminf(fmaxf(rintf(v.w / s), -127.f), 127.f);
        q8[i] = pack4i(qa, qb, qc, qd);
        float ra = fminf(fmaxf(rintf((v.x - qa * s) / s2), -127.f), 127.f);
        float rb = fminf(fmaxf(rintf((v.y - qb * s) / s2), -127.f), 127.f);
        float rc = fminf(fmaxf(rintf((v.z - qc * s) / s2), -127.f), 127.f);
        float rd = fminf(fmaxf(rintf((v.w - qd * s) / s2), -127.f), 127.f);
        r8[i] = pack4i(ra, rb, rc, rd);
    }
}

// all 3 weight packs in one launch
__global__ void pack_w_k(const float4* __restrict__ wq, const float4* __restrict__ wk,
                         const float4* __restrict__ wv, int* __restrict__ yq,
                         int* __restrict__ yk, int* __restrict__ yv, int n4) {
    int z = blockIdx.z;
    const float4* x = (z == 0) ? wq : (z == 1) ? wk : wv;
    int* y = (z == 0) ? yq : (z == 1) ? yk : yv;
    float s = fmaxf(__uint_as_float(g_absmax[z + 1]), 1e-8f) / 7.0f;
    for (int i = blockIdx.x * blockDim.x + threadIdx.x; i < n4; i += gridDim.x * blockDim.x) {
        float4 v = x[i];
        float a = fminf(fmaxf(rintf(v.x / s), -7.f), 7.f);
        float b = fminf(fmaxf(rintf(v.y / s), -7.f), 7.f);
        float c = fminf(fmaxf(rintf(v.z / s), -7.f), 7.f);
        float d = fminf(fmaxf(rintf(v.w / s), -7.f), 7.f);
        y[i] = pack4i(a, b, c, d);
    }
}

// ---------------- int8 dp4a GEMMs -------------------------------------------
__global__ __launch_bounds__(256) void gemm_qk(
    const int* __restrict__ A8, const int* __restrict__ Wq8, const int* __restrict__ Wk8,
    float* __restrict__ Qo, float* __restrict__ Ko)
{
    __shared__ int As[8][128];
    __shared__ int Bs[8][128];
    int z = blockIdx.z;
    const int* W = z ? Wk8 : Wq8;
    float*     O = z ? Ko : Qo;

    int tid = threadIdx.x;
    int tx = tid & 15, ty = tid >> 4;
    int m0 = blockIdx.y * 128, n0 = blockIdx.x * 128;
    int lrow = tid >> 1, lk = (tid & 1) * 4;
    const int* Ag = A8 + (m0 + lrow) * 256 + lk;
    const int* Wg = W  + (n0 + lrow) * 256 + lk;

    int c[8][8] = {};
    for (int kt = 0; kt < 256; kt += 8) {
        int4 av = *(const int4*)(Ag + kt);
        int4 wv = *(const int4*)(Wg + kt);
        As[lk + 0][lrow] = av.x; As[lk + 1][lrow] = av.y;
        As[lk + 2][lrow] = av.z; As[lk + 3][lrow] = av.w;
        Bs[lk + 0][lrow] = wv.x; Bs[lk + 1][lrow] = wv.y;
        Bs[lk + 2][lrow] = wv.z; Bs[lk + 3][lrow] = wv.w;
        __syncthreads();
#pragma unroll
        for (int k = 0; k < 8; k++) {
            int4 a0 = *(const int4*)&As[k][ty * 8];
            int4 a1 = *(const int4*)&As[k][ty * 8 + 4];
            int4 b0 = *(const int4*)&Bs[k][tx * 8];
            int4 b1 = *(const int4*)&Bs[k][tx * 8 + 4];
            int a[8] = {a0.x, a0.y, a0.z, a0.w, a1.x, a1.y, a1.z, a1.w};
            int b[8] = {b0.x, b0.y, b0.z, b0.w, b1.x, b1.y, b1.z, b1.w};
#pragma unroll
            for (int i = 0; i < 8; i++)
#pragma unroll
                for (int j = 0; j < 8; j++)
                    c[i][j] = __dp4a(a[i], b[j], c[i][j]);
        }
        __syncthreads();
    }

    float sa = fmaxf(__uint_as_float(g_absmax[0]), 1e-8f) / 127.0f;
    float sw = fmaxf(__uint_as_float(g_absmax[z + 1]), 1e-8f) / 7.0f;
    float scale = sa * sw;
#pragma unroll
    for (int i = 0; i < 8; i++) {
        int m = m0 + ty * 8 + i;
        int bb = m >> 10, s = m & 1023;
#pragma unroll
        for (int j = 0; j < 8; j++) {
            int n = n0 + tx * 8 + j;
            int h = n >> 6, dh = n & 63;
            O[((bb * 16 + h) << 16) + (s << 6) + dh] = (float)c[i][j] * scale;
        }
    }
}

__global__ __launch_bounds__(256) void gemm_v(
    const int* __restrict__ A8, const int* __restrict__ R8,
    const int* __restrict__ Wv8, float* __restrict__ Vo)
{
    __shared__ int As[8][128];
    __shared__ int Rs[8][128];
    __shared__ int Bs[8][128];

    int tid = threadIdx.x;
    int tx = tid & 15, ty = tid >> 4;
    int m0 = blockIdx.y * 128, n0 = blockIdx.x * 128;
    int lrow = tid >> 1, lk = (tid & 1) * 4;
    const int* Ag = A8  + (m0 + lrow) * 256 + lk;
    const int* Rg = R8  + (m0 + lrow) * 256 + lk;
    const int* Wg = Wv8 + (n0 + lrow) * 256 + lk;

    int c1[8][8] = {};
    int c2[8][8] = {};
    for (int kt = 0; kt < 256; kt += 8) {
        int4 av = *(const int4*)(Ag + kt);
        int4 rv = *(const int4*)(Rg + kt);
        int4 wv = *(const int4*)(Wg + kt);
        As[lk + 0][lrow] = av.x; As[lk + 1][lrow] = av.y;
        As[lk + 2][lrow] = av.z; As[lk + 3][lrow] = av.w;
        Rs[lk + 0][lrow] = rv.x; Rs[lk + 1][lrow] = rv.y;
        Rs[lk + 2][lrow] = rv.z; Rs[lk + 3][lrow] = rv.w;
        Bs[lk + 0][lrow] = wv.x; Bs[lk + 1][lrow] = wv.y;
        Bs[lk + 2][lrow] = wv.z; Bs[lk + 3][lrow] = wv.w;
        __syncthreads();
#pragma unroll
        for (int k = 0; k < 8; k++) {
            int4 a0 = *(const int4*)&As[k][ty * 8];
            int4 a1 = *(const int4*)&As[k][ty * 8 + 4];
            int4 r0 = *(const int4*)&Rs[k][ty * 8];
            int4 r1 = *(const int4*)&Rs[k][ty * 8 + 4];
            int4 b0 = *(const int4*)&Bs[k][tx * 8];
            int4 b1 = *(const int4*)&Bs[k][tx * 8 + 4];
            int a[8] = {a0.x, a0.y, a0.z, a0.w, a1.x, a1.y, a1.z, a1.w};
            int r[8] = {r0.x, r0.y, r0.z, r0.w, r1.x, r1.y, r1.z, r1.w};
            int b[8] = {b0.x, b0.y, b0.z, b0.w, b1.x, b1.y, b1.z, b1.w};
#pragma unroll
            for (int i = 0; i < 8; i++)
#pragma unroll
                for (int j = 0; j < 8; j++) {
                    c1[i][j] = __dp4a(a[i], b[j], c1[i][j]);
                    c2[i][j] = __dp4a(r[i], b[j], c2[i][j]);
                }
        }
        __syncthreads();
    }

    float sa = fmaxf(__uint_as_float(g_absmax[0]), 1e-8f) / 127.0f;
    float sv = fmaxf(__uint_as_float(g_absmax[3]), 1e-8f) / 7.0f;
    float k1 = sa * sv;
    float k2 = (sa / 254.0f) * sv;
#pragma unroll
    for (int i = 0; i < 8; i++) {
        int m = m0 + ty * 8 + i;
        int bb = m >> 10, s = m & 1023;
#pragma unroll
        for (int j = 0; j < 8; j++) {
            int n = n0 + tx * 8 + j;
            int h = n >> 6, dh = n & 63;
            Vo[((bb * 16 + h) << 16) + (s << 6) + dh] =
                fmaf((float)c2[i][j], k2, (float)c1[i][j] * k1);
        }
    }
}

// ---------------- JAX threefry2x32 noise (partitionable, key=(0,42)) --------
__device__ __forceinline__ uint32_t rotl32(uint32_t x, int r) {
    return (x << r) | (x >> (32 - r));
}

__device__ __forceinline__ void threefry2x32(uint32_t c0, uint32_t c1,
                                             uint32_t& o0, uint32_t& o1) {
    const uint32_t k0 = 0u, k1 = 42u, k2 = 0u ^ 42u ^ 0x1BD11BDAu;
    uint32_t x0 = c0 + k0, x1 = c1 + k1;
#define TF_R(r) { x0 += x1; x1 = rotl32(x1, r); x1 ^= x0; }
    TF_R(13) TF_R(15) TF_R(26) TF_R(6)
    x0 += k1; x1 += k2 + 1u;
    TF_R(17) TF_R(29) TF_R(16) TF_R(24)
    x0 += k2; x1 += k0 + 2u;
    TF_R(13) TF_R(15) TF_R(26) TF_R(6)
    x0 += k0; x1 += k1 + 3u;
    TF_R(17) TF_R(29) TF_R(16) TF_R(24)
    x0 += k1; x1 += k2 + 4u;
    TF_R(13) TF_R(15) TF_R(26) TF_R(6)
    x0 += k2; x1 += k0 + 5u;
#undef TF_R
    o0 = x0; o1 = x1;
}

__device__ __forceinline__ float noise_at(unsigned int i) {
    uint32_t o0, o1;
    threefry2x32(0u, i, o0, o1);
    uint32_t bits = o0 ^ o1;
    float f = __uint_as_float((bits >> 9) | 0x3f800000u) - 1.0f;
    const float lo = -0.99999994f;
    float u = fmaxf(lo, fmaf(f, 2.0f, lo));
    float t = fmaf(-u, u, 1.0f);
    float w = -__logf(t);
    float p;
    if (w < 5.0f) {
        w = w - 2.5f;
        p = 2.81022636e-08f;
        p = fmaf(p, w, 3.43273939e-07f);
        p = fmaf(p, w, -3.5233877e-06f);
        p = fmaf(p, w, -4.39150654e-06f);
        p = fmaf(p, w, 0.00021858087f);
        p = fmaf(p, w, -0.00125372503f);
        p = fmaf(p, w, -0.00417768164f);
        p = fmaf(p, w, 0.246640727f);
        p = fmaf(p, w, 1.50140941f);
    } else {
        w = sqrtf(w) - 3.0f;
        p = -0.000200214257f;
        p = fmaf(p, w, 0.000100950558f);
        p = fmaf(p, w, 0.00134934322f);
        p = fmaf(p, w, -0.00367342844f);
        p = fmaf(p, w, 0.00573950773f);
        p = fmaf(p, w, -0.0076224613f);
        p = fmaf(p, w, 0.00943887047f);
        p = fmaf(p, w, 1.00167406f);
        p = fmaf(p, w, 2.83297682f);
    }
    return 1.41421356f * (p * u) * 0.05f;
}

// ---------------- fused flash attention (128q tiles, 8x4 thread tiles) -------
// grid (64 bh, 8 q-tiles), 256 threads as 16tx x 16ty.
// Thread owns 8q x 4k scores and 8q x 4dh output.
// smem words: Qt[64][132] | Kt[64][68] | Pt[64][132] | Vs[64][64]
#define QT_OFF 0
#define KT_OFF 8448
#define PT_OFF 12800
#define VS_OFF 21248
#define SM_WORDS 25344

__global__ __launch_bounds__(256, 2) void attn_k(
    const float* __restrict__ Q, const float* __restrict__ K,
    const float* __restrict__ V, const float* __restrict__ mask,
    float* __restrict__ out)
{
    extern __shared__ float sm[];
    float* Qt = sm + QT_OFF;
    float* Kt = sm + KT_OFF;
    float* Pt = sm + PT_OFF;
    float* Vs = sm + VS_OFF;

    int bh = blockIdx.x, qt = blockIdx.y;
    int b = bh >> 4, h = bh & 15;
    int tid = threadIdx.x, tx = tid & 15, ty = tid >> 4;

    // load + transpose Q tile [128 q][64 d] -> Qt[d][q]
    const float4* Qg = (const float4*)(Q + (bh * 1024 + qt * 128) * 64);
    for (int i = tid; i < 2048; i += 256) {
        float4 v = Qg[i];
        int q = i >> 4, d4 = (i & 15) * 4;
        Qt[(d4 + 0) * 132 + q] = v.x; Qt[(d4 + 1) * 132 + q] = v.y;
        Qt[(d4 + 2) * 132 + q] = v.z; Qt[(d4 + 3) * 132 + q] = v.w;
    }

    float m_[8], l_[8], o_[8][4];
#pragma unroll
    for (int i = 0; i < 8; i++) {
        m_[i] = -1e30f; l_[i] = 0.f;
#pragma unroll
        for (int j = 0; j < 4; j++) o_[i][j] = 0.f;
    }

    const float* maskb = mask + (b << 10);

    for (int kt = 0; kt < 16; kt++) {
        __syncthreads();
        const float4* Kg = (const float4*)(K + (bh * 1024 + kt * 64) * 64);
        const float4* Vg = (const float4*)(V + (bh * 1024 + kt * 64) * 64);
        for (int i = tid; i < 1024; i += 256) {
            float4 kv = Kg[i];
            int k = i >> 4, d4 = (i & 15) * 4;
            Kt[(d4 + 0) * 68 + k] = kv.x; Kt[(d4 + 1) * 68 + k] = kv.y;
            Kt[(d4 + 2) * 68 + k] = kv.z; Kt[(d4 + 3) * 68 + k] = kv.w;
            ((float4*)Vs)[i] = Vg[i];
        }
        __syncthreads();

        // S = Q K^T outer products over d: 8q x 4k per thread
        float s[8][4] = {};
#pragma unroll 16
        for (int d = 0; d < 64; d++) {
            float4 qa4 = *(const float4*)&Qt[d * 132 + ty * 8];
            float4 qb4 = *(const float4*)&Qt[d * 132 + ty * 8 + 4];
            float4 k4  = *(const float4*)&Kt[d * 68 + tx * 4];
            float qa[8] = {qa4.x, qa4.y, qa4.z, qa4.w, qb4.x, qb4.y, qb4.z, qb4.w};
            float ka[4] = {k4.x, k4.y, k4.z, k4.w};
#pragma unroll
            for (int i = 0; i < 8; i++)
#pragma unroll
                for (int j = 0; j < 4; j++)
                    s[i][j] = fmaf(qa[i], ka[j], s[i][j]);
        }

        // scale + noise + mask
        float4 mv4 = *(const float4*)&maskb[kt * 64 + tx * 4];
        float mv[4] = {mv4.x, mv4.y, mv4.z, mv4.w};
        unsigned base = ((unsigned)bh << 20) | ((unsigned)(qt * 128 + ty * 8) << 10)
                        | (unsigned)(kt * 64 + tx * 4);
#pragma unroll
        for (int i = 0; i < 8; i++)
#pragma unroll
            for (int j = 0; j < 4; j++)
                s[i][j] = fmaf(s[i][j], 0.125f, noise_at(base + (i << 10) + j) + mv[j]);

        // online softmax: row stats reduce across tx (low 4 lane bits)
#pragma unroll
        for (int i = 0; i < 8; i++) {
            float tm = fmaxf(fmaxf(s[i][0], s[i][1]), fmaxf(s[i][2], s[i][3]));
            tm = fmaxf(tm, __shfl_xor_sync(0xffffffffu, tm, 1));
            tm = fmaxf(tm, __shfl_xor_sync(0xffffffffu, tm, 2));
            tm = fmaxf(tm, __shfl_xor_sync(0xffffffffu, tm, 4));
            tm = fmaxf(tm, __shfl_xor_sync(0xffffffffu, tm, 8));
            float mnew = fmaxf(m_[i], tm);
            float corr = __expf(m_[i] - mnew);
            float ps = 0.f;
#pragma unroll
            for (int j = 0; j < 4; j++) { s[i][j] = __expf(s[i][j] - mnew); ps += s[i][j]; }
            ps += __shfl_xor_sync(0xffffffffu, ps, 1);
            ps += __shfl_xor_sync(0xffffffffu, ps, 2);
            ps += __shfl_xor_sync(0xffffffffu, ps, 4);
            ps += __shfl_xor_sync(0xffffffffu, ps, 8);
            l_[i] = l_[i] * corr + ps;
            m_[i] = mnew;
#pragma unroll
            for (int j = 0; j < 4; j++) o_[i][j] *= corr;
        }

        // P^T to smem (k-major): Pt[k][q]
#pragma unroll
        for (int j = 0; j < 4; j++) {
            *(float4*)&Pt[(tx * 4 + j) * 132 + ty * 8] =
                make_float4(s[0][j], s[1][j], s[2][j], s[3][j]);
            *(float4*)&Pt[(tx * 4 + j) * 132 + ty * 8 + 4] =
                make_float4(s[4][j], s[5][j], s[6][j], s[7][j]);
        }
        __syncthreads();

        // O += P V outer products over k: 8q x 4dh per thread
#pragma unroll 8
        for (int k = 0; k < 64; k++) {
            float4 pa4 = *(const float4*)&Pt[k * 132 + ty * 8];
            float4 pb4 = *(const float4*)&Pt[k * 132 + ty * 8 + 4];
            float4 v4  = *(const float4*)&Vs[k * 64 + tx * 4];
            float pa[8] = {pa4.x, pa4.y, pa4.z, pa4.w, pb4.x, pb4.y, pb4.z, pb4.w};
            float va[4] = {v4.x, v4.y, v4.z, v4.w};
#pragma unroll
            for (int i = 0; i < 8; i++)
#pragma unroll
                for (int j = 0; j < 4; j++)
                    o_[i][j] = fmaf(pa[i], va[j], o_[i][j]);
        }
    }

#pragma unroll
    for (int i = 0; i < 8; i++) {
        float inv = 1.0f / l_[i];
        int sI = qt * 128 + ty * 8 + i;
        *(float4*)(out + ((size_t)((b << 10) + sI)) * 1024 + (h << 6) + tx * 4) =
            make_float4(o_[i][0] * inv, o_[i][1] * inv, o_[i][2] * inv, o_[i][3] * inv);
    }
}

// ---------------- launch -----------------------------------------------------
extern "C" void kernel_launch(void* const* d_in, const int* in_sizes, int n_in,
                              void* d_out, int out_size) {
    const float* hidden = (const float*)d_in[0];
    const float* mask   = (const float*)d_in[1];
    const float* Wq     = (const float*)d_in[2];
    const float* Wk     = (const float*)d_in[3];
    const float* Wv     = (const float*)d_in[4];
    float* out = (float*)d_out;

    int *hq8, *r8, *wq8, *wk8, *wv8;
    float *Qp, *Kp, *Vp;
    cudaGetSymbolAddress((void**)&hq8, g_hq8);
    cudaGetSymbolAddress((void**)&r8,  g_r8);
    cudaGetSymbolAddress((void**)&wq8, g_wq8);
    cudaGetSymbolAddress((void**)&wk8, g_wk8);
    cudaGetSymbolAddress((void**)&wv8, g_wv8);
    cudaGetSymbolAddress((void**)&Qp,  g_Q);
    cudaGetSymbolAddress((void**)&Kp,  g_K);
    cudaGetSymbolAddress((void**)&Vp,  g_V);

    init_k<<<1, 32>>>();
    absmax4_k<<<512, 256>>>((const float4*)hidden, 1048576, 0);
    absmax_w_k<<<dim3(128, 1, 3), 256>>>((const float4*)Wq, (const float4*)Wk,
                                         (const float4*)Wv, 262144);

    pack_act_k<<<1024, 256>>>((const float4*)hidden, hq8, r8, 1048576);
    pack_w_k<<<dim3(256, 1, 3), 256>>>((const float4*)Wq, (const float4*)Wk,
                                       (const float4*)Wv, wq8, wk8, wv8, 262144);

    gemm_qk<<<dim3(8, 32, 2), 256>>>(hq8, wq8, wk8, Qp, Kp);
    gemm_v<<<dim3(8, 32), 256>>>(hq8, r8, wv8, Vp);

    cudaFuncSetAttribute(attn_k, cudaFuncAttributeMaxDynamicSharedMemorySize, SM_WORDS * 4);
    attn_k<<<dim3(64, 8), 256, SM_WORDS * 4>>>(Qp, Kp, Vp, mask, out);
}

// round 6
// speedup vs baseline: 1.1240x; 1.1240x over previous
#include <cuda_runtime.h>
#include <cuda_fp16.h>
#include <cstdint>

// ---------------- scratch (__device__ globals; no allocs allowed) ------------
__device__ int      g_hq8[1048576];   // hidden quantized int8, packed 4/int32
__device__ int      g_r8 [1048576];   // residual quantized int8, packed
__device__ int      g_wq8[262144];
__device__ int      g_wk8[262144];
__device__ int      g_wv8[262144];
__device__ unsigned g_Qh[4194304];    // [B*H, S, 64] packed {fp16 hi, fp16 lo}
__device__ unsigned g_Kh[4194304];
__device__ unsigned g_Vh[4194304];
__device__ unsigned int g_absmax[4];  // 0:hidden 1:Wq 2:Wk 3:Wv

// ---------------- absmax / packing ------------------------------------------
__global__ void init_k() {
    if (threadIdx.x < 4) g_absmax[threadIdx.x] = 0u;
}

__global__ void absmax4_k(const float4* __restrict__ x, int n4, int slot) {
    float m = 0.f;
    for (int i = blockIdx.x * blockDim.x + threadIdx.x; i < n4; i += gridDim.x * blockDim.x) {
        float4 v = x[i];
        m = fmaxf(m, fmaxf(fmaxf(fabsf(v.x), fabsf(v.y)), fmaxf(fabsf(v.z), fabsf(v.w))));
    }
#pragma unroll
    for (int o = 16; o > 0; o >>= 1) m = fmaxf(m, __shfl_xor_sync(0xffffffffu, m, o));
    if ((threadIdx.x & 31) == 0) atomicMax(&g_absmax[slot], __float_as_uint(m));
}

__global__ void absmax_w_k(const float4* __restrict__ wq, const float4* __restrict__ wk,
                           const float4* __restrict__ wv, int n4) {
    int z = blockIdx.z;
    const float4* x = (z == 0) ? wq : (z == 1) ? wk : wv;
    float m = 0.f;
    for (int i = blockIdx.x * blockDim.x + threadIdx.x; i < n4; i += gridDim.x * blockDim.x) {
        float4 v = x[i];
        m = fmaxf(m, fmaxf(fmaxf(fabsf(v.x), fabsf(v.y)), fmaxf(fabsf(v.z), fabsf(v.w))));
    }
#pragma unroll
    for (int o = 16; o > 0; o >>= 1) m = fmaxf(m, __shfl_xor_sync(0xffffffffu, m, o));
    if ((threadIdx.x & 31) == 0) atomicMax(&g_absmax[z + 1], __float_as_uint(m));
}

__device__ __forceinline__ int pack4i(float a, float b, float c, float d) {
    int ia = (int)a, ib = (int)b, ic = (int)c, id = (int)d;
    return (ia & 0xFF) | ((ib & 0xFF) << 8) | ((ic & 0xFF) << 16) | ((id & 0xFF) << 24);
}

__global__ void pack_act_k(const float4* __restrict__ x, int* __restrict__ q8,
                           int* __restrict__ r8, int n4) {
    float s  = fmaxf(__uint_as_float(g_absmax[0]), 1e-8f) / 127.0f;
    float s2 = s / 254.0f;
    for (int i = blockIdx.x * blockDim.x + threadIdx.x; i < n4; i += gridDim.x * blockDim.x) {
        float4 v = x[i];
        float qa = fminf(fmaxf(rintf(v.x / s), -127.f), 127.f);
        float qb = fminf(fmaxf(rintf(v.y / s), -127.f), 127.f);
        float qc = fminf(fmaxf(rintf(v.z / s), -127.f), 127.f);
        float qd = fminf(fmaxf(rintf(v.w / s), -127.f), 127.f);
        q8[i] = pack4i(qa, qb, qc, qd);
        float ra = fminf(fmaxf(rintf((v.x - qa * s) / s2), -127.f), 127.f);
        float rb = fminf(fmaxf(rintf((v.y - qb * s) / s2), -127.f), 127.f);
        float rc = fminf(fmaxf(rintf((v.z - qc * s) / s2), -127.f), 127.f);
        float rd = fminf(fmaxf(rintf((v.w - qd * s) / s2), -127.f), 127.f);
        r8[i] = pack4i(ra, rb, rc, rd);
    }
}

__global__ void pack_w_k(const float4* __restrict__ wq, const float4* __restrict__ wk,
                         const float4* __restrict__ wv, int* __restrict__ yq,
                         int* __restrict__ yk, int* __restrict__ yv, int n4) {
    int z = blockIdx.z;
    const float4* x = (z == 0) ? wq : (z == 1) ? wk : wv;
    int* y = (z == 0) ? yq : (z == 1) ? yk : yv;
    float s = fmaxf(__uint_as_float(g_absmax[z + 1]), 1e-8f) / 7.0f;
    for (int i = blockIdx.x * blockDim.x + threadIdx.x; i < n4; i += gridDim.x * blockDim.x) {
        float4 v = x[i];
        float a = fminf(fmaxf(rintf(v.x / s), -7.f), 7.f);
        float b = fminf(fmaxf(rintf(v.y / s), -7.f), 7.f);
        float c = fminf(fmaxf(rintf(v.z / s), -7.f), 7.f);
        float d = fminf(fmaxf(rintf(v.w / s), -7.f), 7.f);
        y[i] = pack4i(a, b, c, d);
    }
}

// fp32 -> packed {half hi, half lo}; x == hi + lo to ~2^-22 relative
__device__ __forceinline__ unsigned pack_f2h(float x) {
    __half h = __float2half_rn(x);
    __half l = __float2half_rn(x - __half2float(h));
    return (unsigned)__half_as_ushort(h) | ((unsigned)__half_as_ushort(l) << 16);
}

// ---------------- int8 dp4a GEMMs (epilogue packs hi/lo fp16) ----------------
__global__ __launch_bounds__(256) void gemm_qk(
    const int* __restrict__ A8, const int* __restrict__ Wq8, const int* __restrict__ Wk8,
    unsigned* __restrict__ Qo, unsigned* __restrict__ Ko)
{
    __shared__ int As[8][128];
    __shared__ int Bs[8][128];
    int z = blockIdx.z;
    const int* W = z ? Wk8 : Wq8;
    unsigned*  O = z ? Ko : Qo;

    int tid = threadIdx.x;
    int tx = tid & 15, ty = tid >> 4;
    int m0 = blockIdx.y * 128, n0 = blockIdx.x * 128;
    int lrow = tid >> 1, lk = (tid & 1) * 4;
    const int* Ag = A8 + (m0 + lrow) * 256 + lk;
    const int* Wg = W  + (n0 + lrow) * 256 + lk;

    int c[8][8] = {};
    for (int kt = 0; kt < 256; kt += 8) {
        int4 av = *(const int4*)(Ag + kt);
        int4 wv = *(const int4*)(Wg + kt);
        As[lk + 0][lrow] = av.x; As[lk + 1][lrow] = av.y;
        As[lk + 2][lrow] = av.z; As[lk + 3][lrow] = av.w;
        Bs[lk + 0][lrow] = wv.x; Bs[lk + 1][lrow] = wv.y;
        Bs[lk + 2][lrow] = wv.z; Bs[lk + 3][lrow] = wv.w;
        __syncthreads();
#pragma unroll
        for (int k = 0; k < 8; k++) {
            int4 a0 = *(const int4*)&As[k][ty * 8];
            int4 a1 = *(const int4*)&As[k][ty * 8 + 4];
            int4 b0 = *(const int4*)&Bs[k][tx * 8];
            int4 b1 = *(const int4*)&Bs[k][tx * 8 + 4];
            int a[8] = {a0.x, a0.y, a0.z, a0.w, a1.x, a1.y, a1.z, a1.w};
            int b[8] = {b0.x, b0.y, b0.z, b0.w, b1.x, b1.y, b1.z, b1.w};
#pragma unroll
            for (int i = 0; i < 8; i++)
#pragma unroll
                for (int j = 0; j < 8; j++)
                    c[i][j] = __dp4a(a[i], b[j], c[i][j]);
        }
        __syncthreads();
    }

    float sa = fmaxf(__uint_as_float(g_absmax[0]), 1e-8f) / 127.0f;
    float sw = fmaxf(__uint_as_float(g_absmax[z + 1]), 1e-8f) / 7.0f;
    float scale = sa * sw;
#pragma unroll
    for (int i = 0; i < 8; i++) {
        int m = m0 + ty * 8 + i;
        int bb = m >> 10, s = m & 1023;
#pragma unroll
        for (int j = 0; j < 8; j++) {
            int n = n0 + tx * 8 + j;
            int h = n >> 6, dh = n & 63;
            O[((bb * 16 + h) << 16) + (s << 6) + dh] = pack_f2h((float)c[i][j] * scale);
        }
    }
}

__global__ __launch_bounds__(256) void gemm_v(
    const int* __restrict__ A8, const int* __restrict__ R8,
    const int* __restrict__ Wv8, unsigned* __restrict__ Vo)
{
    __shared__ int As[8][128];
    __shared__ int Rs[8][128];
    __shared__ int Bs[8][128];

    int tid = threadIdx.x;
    int tx = tid & 15, ty = tid >> 4;
    int m0 = blockIdx.y * 128, n0 = blockIdx.x * 128;
    int lrow = tid >> 1, lk = (tid & 1) * 4;
    const int* Ag = A8  + (m0 + lrow) * 256 + lk;
    const int* Rg = R8  + (m0 + lrow) * 256 + lk;
    const int* Wg = Wv8 + (n0 + lrow) * 256 + lk;

    int c1[8][8] = {};
    int c2[8][8] = {};
    for (int kt = 0; kt < 256; kt += 8) {
        int4 av = *(const int4*)(Ag + kt);
        int4 rv = *(const int4*)(Rg + kt);
        int4 wv = *(const int4*)(Wg + kt);
        As[lk + 0][lrow] = av.x; As[lk + 1][lrow] = av.y;
        As[lk + 2][lrow] = av.z; As[lk + 3][lrow] = av.w;
        Rs[lk + 0][lrow] = rv.x; Rs[lk + 1][lrow] = rv.y;
        Rs[lk + 2][lrow] = rv.z; Rs[lk + 3][lrow] = rv.w;
        Bs[lk + 0][lrow] = wv.x; Bs[lk + 1][lrow] = wv.y;
        Bs[lk + 2][lrow] = wv.z; Bs[lk + 3][lrow] = wv.w;
        __syncthreads();
#pragma unroll
        for (int k = 0; k < 8; k++) {
            int4 a0 = *(const int4*)&As[k][ty * 8];
            int4 a1 = *(const int4*)&As[k][ty * 8 + 4];
            int4 r0 = *(const int4*)&Rs[k][ty * 8];
            int4 r1 = *(const int4*)&Rs[k][ty * 8 + 4];
            int4 b0 = *(const int4*)&Bs[k][tx * 8];
            int4 b1 = *(const int4*)&Bs[k][tx * 8 + 4];
            int a[8] = {a0.x, a0.y, a0.z, a0.w, a1.x, a1.y, a1.z, a1.w};
            int r[8] = {r0.x, r0.y, r0.z, r0.w, r1.x, r1.y, r1.z, r1.w};
            int b[8] = {b0.x, b0.y, b0.z, b0.w, b1.x, b1.y, b1.z, b1.w};
#pragma unroll
            for (int i = 0; i < 8; i++)
#pragma unroll
                for (int j = 0; j < 8; j++) {
                    c1[i][j] = __dp4a(a[i], b[j], c1[i][j]);
                    c2[i][j] = __dp4a(r[i], b[j], c2[i][j]);
                }
        }
        __syncthreads();
    }

    float sa = fmaxf(__uint_as_float(g_absmax[0]), 1e-8f) / 127.0f;
    float sv = fmaxf(__uint_as_float(g_absmax[3]), 1e-8f) / 7.0f;
    float k1 = sa * sv;
    float k2 = (sa / 254.0f) * sv;
#pragma unroll
    for (int i = 0; i < 8; i++) {
        int m = m0 + ty * 8 + i;
        int bb = m >> 10, s = m & 1023;
#pragma unroll
        for (int j = 0; j < 8; j++) {
            int n = n0 + tx * 8 + j;
            int h = n >> 6, dh = n & 63;
            Vo[((bb * 16 + h) << 16) + (s << 6) + dh] =
                pack_f2h(fmaf((float)c2[i][j], k2, (float)c1[i][j] * k1));
        }
    }
}

// ---------------- JAX threefry2x32 noise (partitionable, key=(0,42)) --------
__device__ __forceinline__ uint32_t rotl32(uint32_t x, int r) {
    return (x << r) | (x >> (32 - r));
}

__device__ __forceinline__ void threefry2x32(uint32_t c0, uint32_t c1,
                                             uint32_t& o0, uint32_t& o1) {
    const uint32_t k0 = 0u, k1 = 42u, k2 = 0u ^ 42u ^ 0x1BD11BDAu;
    uint32_t x0 = c0 + k0, x1 = c1 + k1;
#define TF_R(r) { x0 += x1; x1 = rotl32(x1, r); x1 ^= x0; }
    TF_R(13) TF_R(15) TF_R(26) TF_R(6)
    x0 += k1; x1 += k2 + 1u;
    TF_R(17) TF_R(29) TF_R(16) TF_R(24)
    x0 += k2; x1 += k0 + 2u;
    TF_R(13) TF_R(15) TF_R(26) TF_R(6)
    x0 += k0; x1 += k1 + 3u;
    TF_R(17) TF_R(29) TF_R(16) TF_R(24)
    x0 += k1; x1 += k2 + 4u;
    TF_R(13) TF_R(15) TF_R(26) TF_R(6)
    x0 += k2; x1 += k0 + 5u;
#undef TF_R
    o0 = x0; o1 = x1;
}

__device__ __forceinline__ float noise_at(unsigned int i) {
    uint32_t o0, o1;
    threefry2x32(0u, i, o0, o1);
    uint32_t bits = o0 ^ o1;
    float f = __uint_as_float((bits >> 9) | 0x3f800000u) - 1.0f;
    const float lo = -0.99999994f;
    float u = fmaxf(lo, fmaf(f, 2.0f, lo));
    float t = fmaf(-u, u, 1.0f);
    float w = -__logf(t);
    float p;
    if (w < 5.0f) {
        w = w - 2.5f;
        p = 2.81022636e-08f;
        p = fmaf(p, w, 3.43273939e-07f);
        p = fmaf(p, w, -3.5233877e-06f);
        p = fmaf(p, w, -4.39150654e-06f);
        p = fmaf(p, w, 0.00021858087f);
        p = fmaf(p, w, -0.00125372503f);
        p = fmaf(p, w, -0.00417768164f);
        p = fmaf(p, w, 0.246640727f);
        p = fmaf(p, w, 1.50140941f);
    } else {
        w = sqrtf(w) - 3.0f;
        p = -0.000200214257f;
        p = fmaf(p, w, 0.000100950558f);
        p = fmaf(p, w, 0.00134934322f);
        p = fmaf(p, w, -0.00367342844f);
        p = fmaf(p, w, 0.00573950773f);
        p = fmaf(p, w, -0.0076224613f);
        p = fmaf(p, w, 0.00943887047f);
        p = fmaf(p, w, 1.00167406f);
        p = fmaf(p, w, 2.83297682f);
    }
    return 1.41421356f * (p * u) * 0.05f;
}

// ---------------- HMMA helpers ----------------------------------------------
__device__ __forceinline__ void mma16816(float& c0, float& c1, float& c2, float& c3,
                                         unsigned a0, unsigned a1, unsigned a2, unsigned a3,
                                         unsigned b0, unsigned b1) {
    asm volatile(
        "mma.sync.aligned.m16n8k16.row.col.f32.f16.f16.f32 "
        "{%0,%1,%2,%3},{%4,%5,%6,%7},{%8,%9},{%0,%1,%2,%3};"
        : "+f"(c0), "+f"(c1), "+f"(c2), "+f"(c3)
        : "r"(a0), "r"(a1), "r"(a2), "r"(a3), "r"(b0), "r"(b1));
}

__device__ __forceinline__ unsigned h2pack(float x, float y) {
    __half2 h = __float22half2_rn(make_float2(x, y));
    return *(unsigned*)&h;
}

// ---------------- fused flash attention (HMMA, hi/lo fp16 split) -------------
// grid (64 bh, 16 qt); 128 threads = 4 warps; warp w owns q rows [w*16, w*16+16).
// K/V tiles of 64. smem planes (unsigned short, row stride 72):
//   Qhi/Qlo: [64 q][64 d]   Khi/Klo: [64 k][64 d]   Vthi/Vtlo: [64 dh][64 k]
#define PLANE 4608   // 64*72 halves
__global__ __launch_bounds__(128, 3) void attn_k(
    const unsigned* __restrict__ Q, const unsigned* __restrict__ K,
    const unsigned* __restrict__ V, const float* __restrict__ mask,
    float* __restrict__ out)
{
    extern __shared__ unsigned short smh[];
    unsigned short* qhi = smh;
    unsigned short* qlo = smh + PLANE;
    unsigned short* khi = smh + 2 * PLANE;
    unsigned short* klo = smh + 3 * PLANE;
    unsigned short* vhi = smh + 4 * PLANE;
    unsigned short* vlo = smh + 5 * PLANE;
    float* Ms = (float*)(smh + 6 * PLANE);

    int bh = blockIdx.x, qt = blockIdx.y;
    int b = bh >> 4, h = bh & 15;
    int tid = threadIdx.x, w = tid >> 5, lane = tid & 31;
    int g = lane >> 2, t = lane & 3;

    // ---- load Q tile [64][64] packed hi/lo -> planes
    const unsigned* Qg = Q + (bh * 1024 + qt * 64) * 64;
    for (int i = tid; i < 4096; i += 128) {
        unsigned v = Qg[i];
        int q = i >> 6, d = i & 63;
        qhi[q * 72 + d] = (unsigned short)(v & 0xFFFF);
        qlo[q * 72 + d] = (unsigned short)(v >> 16);
    }
    __syncthreads();

    // ---- Q A-fragments in registers (4 d-chunks x 4 regs, hi & lo)
    unsigned qh[4][4], ql[4][4];
    int qr = w * 16 + g;
#pragma unroll
    for (int c = 0; c < 4; c++) {
        int col = c * 16 + 2 * t;
        qh[c][0] = *(const unsigned*)&qhi[qr * 72 + col];
        qh[c][1] = *(const unsigned*)&qhi[(qr + 8) * 72 + col];
        qh[c][2] = *(const unsigned*)&qhi[qr * 72 + col + 8];
        qh[c][3] = *(const unsigned*)&qhi[(qr + 8) * 72 + col + 8];
        ql[c][0] = *(const unsigned*)&qlo[qr * 72 + col];
        ql[c][1] = *(const unsigned*)&qlo[(qr + 8) * 72 + col];
        ql[c][2] = *(const unsigned*)&qlo[qr * 72 + col + 8];
        ql[c][3] = *(const unsigned*)&qlo[(qr + 8) * 72 + col + 8];
    }

    float m0r = -1e30f, m1r = -1e30f, l0r = 0.f, l1r = 0.f;
    float O[8][4];
#pragma unroll
    for (int n = 0; n < 8; n++)
#pragma unroll
        for (int e = 0; e < 4; e++) O[n][e] = 0.f;

    const float* maskb = mask + (b << 10);
    unsigned base0 = ((unsigned)bh << 20) | ((unsigned)(qt * 64 + qr) << 10);

    for (int kt = 0; kt < 16; kt++) {
        __syncthreads();
        const unsigned* Kg = K + (bh * 1024 + kt * 64) * 64;
        const unsigned* Vg = V + (bh * 1024 + kt * 64) * 64;
        for (int i = tid; i < 4096; i += 128) {
            unsigned kv = Kg[i];
            unsigned vv = Vg[i];
            int k = i >> 6, d = i & 63;
            khi[k * 72 + d] = (unsigned short)(kv & 0xFFFF);
            klo[k * 72 + d] = (unsigned short)(kv >> 16);
            vhi[d * 72 + k] = (unsigned short)(vv & 0xFFFF);   // transposed
            vlo[d * 72 + k] = (unsigned short)(vv >> 16);
        }
        if (tid < 64) Ms[tid] = maskb[kt * 64 + tid];
        __syncthreads();

        // ---- S = Q K^T (3-term hi/lo split)
        float S[8][4];
#pragma unroll
        for (int n = 0; n < 8; n++)
#pragma unroll
            for (int e = 0; e < 4; e++) S[n][e] = 0.f;

#pragma unroll
        for (int j = 0; j < 8; j++) {
            int krow = j * 8 + g;
#pragma unroll
            for (int c = 0; c < 4; c++) {
                int col = c * 16 + 2 * t;
                unsigned bh0 = *(const unsigned*)&khi[krow * 72 + col];
                unsigned bh1 = *(const unsigned*)&khi[krow * 72 + col + 8];
                unsigned bl0 = *(const unsigned*)&klo[krow * 72 + col];
                unsigned bl1 = *(const unsigned*)&klo[krow * 72 + col + 8];
                mma16816(S[j][0], S[j][1], S[j][2], S[j][3],
                         qh[c][0], qh[c][1], qh[c][2], qh[c][3], bh0, bh1);
                mma16816(S[j][0], S[j][1], S[j][2], S[j][3],
                         qh[c][0], qh[c][1], qh[c][2], qh[c][3], bl0, bl1);
                mma16816(S[j][0], S[j][1], S[j][2], S[j][3],
                         ql[c][0], ql[c][1], ql[c][2], ql[c][3], bh0, bh1);
            }
        }

        // ---- scale + noise + mask
#pragma unroll
        for (int j = 0; j < 8; j++) {
            unsigned kc = (unsigned)(kt * 64 + j * 8 + 2 * t);
            float mv0 = Ms[j * 8 + 2 * t], mv1 = Ms[j * 8 + 2 * t + 1];
            S[j][0] = fmaf(S[j][0], 0.125f, noise_at(base0 + kc) + mv0);
            S[j][1] = fmaf(S[j][1], 0.125f, noise_at(base0 + kc + 1) + mv1);
            S[j][2] = fmaf(S[j][2], 0.125f, noise_at(base0 + (8u << 10) + kc) + mv0);
            S[j][3] = fmaf(S[j][3], 0.125f, noise_at(base0 + (8u << 10) + kc + 1) + mv1);
        }

        // ---- online softmax (rows g and g+8; reduce over quad lanes)
        float tm0 = -1e30f, tm1 = -1e30f;
#pragma unroll
        for (int j = 0; j < 8; j++) {
            tm0 = fmaxf(tm0, fmaxf(S[j][0], S[j][1]));
            tm1 = fmaxf(tm1, fmaxf(S[j][2], S[j][3]));
        }
        tm0 = fmaxf(tm0, __shfl_xor_sync(0xffffffffu, tm0, 1));
        tm0 = fmaxf(tm0, __shfl_xor_sync(0xffffffffu, tm0, 2));
        tm1 = fmaxf(tm1, __shfl_xor_sync(0xffffffffu, tm1, 1));
        tm1 = fmaxf(tm1, __shfl_xor_sync(0xffffffffu, tm1, 2));
        float mn0 = fmaxf(m0r, tm0), mn1 = fmaxf(m1r, tm1);
        float cor0 = __expf(m0r - mn0), cor1 = __expf(m1r - mn1);
        m0r = mn0; m1r = mn1;
        float ps0 = 0.f, ps1 = 0.f;
#pragma unroll
        for (int j = 0; j < 8; j++) {
            S[j][0] = __expf(S[j][0] - mn0); S[j][1] = __expf(S[j][1] - mn0);
            S[j][2] = __expf(S[j][2] - mn1); S[j][3] = __expf(S[j][3] - mn1);
            ps0 += S[j][0] + S[j][1];
            ps1 += S[j][2] + S[j][3];
        }
        ps0 += __shfl_xor_sync(0xffffffffu, ps0, 1);
        ps0 += __shfl_xor_sync(0xffffffffu, ps0, 2);
        ps1 += __shfl_xor_sync(0xffffffffu, ps1, 1);
        ps1 += __shfl_xor_sync(0xffffffffu, ps1, 2);
        l0r = l0r * cor0 + ps0;
        l1r = l1r * cor1 + ps1;
#pragma unroll
        for (int n = 0; n < 8; n++) {
            O[n][0] *= cor0; O[n][1] *= cor0;
            O[n][2] *= cor1; O[n][3] *= cor1;
        }

        // ---- P C-frags -> A-frags (register-only), hi/lo split
        unsigned ph[4][4], pl[4][4];
#pragma unroll
        for (int c = 0; c < 4; c++) {
            float v0 = S[2 * c][0],     v1 = S[2 * c][1];
            float v2 = S[2 * c][2],     v3 = S[2 * c][3];
            float v4 = S[2 * c + 1][0], v5 = S[2 * c + 1][1];
            float v6 = S[2 * c + 1][2], v7 = S[2 * c + 1][3];
            ph[c][0] = h2pack(v0, v1);
            ph[c][1] = h2pack(v2, v3);
            ph[c][2] = h2pack(v4, v5);
            ph[c][3] = h2pack(v6, v7);
            __half2* hp;
            hp = (__half2*)&ph[c][0];
            pl[c][0] = h2pack(v0 - __half2float(hp->x), v1 - __half2float(hp->y));
            hp = (__half2*)&ph[c][1];
            pl[c][1] = h2pack(v2 - __half2float(hp->x), v3 - __half2float(hp->y));
            hp = (__half2*)&ph[c][2];
            pl[c][2] = h2pack(v4 - __half2float(hp->x), v5 - __half2float(hp->y));
            hp = (__half2*)&ph[c][3];
            pl[c][3] = h2pack(v6 - __half2float(hp->x), v7 - __half2float(hp->y));
        }

        // ---- O += P V (3-term hi/lo split); V^T planes give B-frags directly
#pragma unroll
        for (int n = 0; n < 8; n++) {
            int vrow = n * 8 + g;
#pragma unroll
            for (int c = 0; c < 4; c++) {
                int col = c * 16 + 2 * t;
                unsigned bh0 = *(const unsigned*)&vhi[vrow * 72 + col];
                unsigned bh1 = *(const unsigned*)&vhi[vrow * 72 + col + 8];
                unsigned bl0 = *(const unsigned*)&vlo[vrow * 72 + col];
                unsigned bl1 = *(const unsigned*)&vlo[vrow * 72 + col + 8];
                mma16816(O[n][0], O[n][1], O[n][2], O[n][3],
                         ph[c][0], ph[c][1], ph[c][2], ph[c][3], bh0, bh1);
                mma16816(O[n][0], O[n][1], O[n][2], O[n][3],
                         ph[c][0], ph[c][1], ph[c][2], ph[c][3], bl0, bl1);
                mma16816(O[n][0], O[n][1], O[n][2], O[n][3],
                         pl[c][0], pl[c][1], pl[c][2], pl[c][3], bh0, bh1);
            }
        }
    }

    // ---- epilogue
    float inv0 = 1.0f / l0r, inv1 = 1.0f / l1r;
    int q0 = qt * 64 + qr;
    float* o0 = out + ((size_t)((b << 10) + q0)) * 1024 + (h << 6);
    float* o1 = out + ((size_t)((b << 10) + q0 + 8)) * 1024 + (h << 6);
#pragma unroll
    for (int n = 0; n < 8; n++) {
        int dh = n * 8 + 2 * t;
        *(float2*)(o0 + dh) = make_float2(O[n][0] * inv0, O[n][1] * inv0);
        *(float2*)(o1 + dh) = make_float2(O[n][2] * inv1, O[n][3] * inv1);
    }
}

// ---------------- launch -----------------------------------------------------
extern "C" void kernel_launch(void* const* d_in, const int* in_sizes, int n_in,
                              void* d_out, int out_size) {
    const float* hidden = (const float*)d_in[0];
    const float* mask   = (const float*)d_in[1];
    const float* Wq     = (const float*)d_in[2];
    const float* Wk     = (const float*)d_in[3];
    const float* Wv     = (const float*)d_in[4];
    float* out = (float*)d_out;

    int *hq8, *r8, *wq8, *wk8, *wv8;
    unsigned *Qp, *Kp, *Vp;
    cudaGetSymbolAddress((void**)&hq8, g_hq8);
    cudaGetSymbolAddress((void**)&r8,  g_r8);
    cudaGetSymbolAddress((void**)&wq8, g_wq8);
    cudaGetSymbolAddress((void**)&wk8, g_wk8);
    cudaGetSymbolAddress((void**)&wv8, g_wv8);
    cudaGetSymbolAddress((void**)&Qp,  g_Qh);
    cudaGetSymbolAddress((void**)&Kp,  g_Kh);
    cudaGetSymbolAddress((void**)&Vp,  g_Vh);

    init_k<<<1, 32>>>();
    absmax4_k<<<512, 256>>>((const float4*)hidden, 1048576, 0);
    absmax_w_k<<<dim3(128, 1, 3), 256>>>((const float4*)Wq, (const float4*)Wk,
                                         (const float4*)Wv, 262144);

    pack_act_k<<<1024, 256>>>((const float4*)hidden, hq8, r8, 1048576);
    pack_w_k<<<dim3(256, 1, 3), 256>>>((const float4*)Wq, (const float4*)Wk,
                                       (const float4*)Wv, wq8, wk8, wv8, 262144);

    gemm_qk<<<dim3(8, 32, 2), 256>>>(hq8, wq8, wk8, Qp, Kp);
    gemm_v<<<dim3(8, 32), 256>>>(hq8, r8, wv8, Vp);

    int smem_bytes = 6 * PLANE * 2 + 64 * 4;   // 6 half planes + mask
    cudaFuncSetAttribute(attn_k, cudaFuncAttributeMaxDynamicSharedMemorySize, smem_bytes);
    attn_k<<<dim3(64, 16), 128, smem_bytes>>>(Qp, Kp, Vp, mask, out);
}

// round 7
// speedup vs baseline: 1.1520x; 1.0249x over previous
#include <cuda_runtime.h>
#include <cuda_fp16.h>
#include <cstdint>

// ---------------- scratch (__device__ globals; no allocs allowed) ------------
__device__ int      g_hq8[1048576];   // hidden quantized int8, packed 4/int32
__device__ int      g_r8 [1048576];   // residual quantized int8, packed
__device__ int      g_wq8[262144];
__device__ int      g_wk8[262144];
__device__ int      g_wv8[262144];
__device__ unsigned g_Qh[4194304];    // [B*H, S, 64] packed {fp16 hi, fp16 lo}
__device__ unsigned g_Kh[4194304];
__device__ unsigned g_Vh[4194304];
__device__ unsigned int g_absmax[4];  // 0:hidden 1:Wq 2:Wk 3:Wv

// ---------------- absmax / packing ------------------------------------------
__global__ void init_k() {
    if (threadIdx.x < 4) g_absmax[threadIdx.x] = 0u;
}

// all 4 absmax reductions in one launch (z = 0 hidden, 1..3 weights)
__global__ void absmax_all_k(const float4* __restrict__ hid, const float4* __restrict__ wq,
                             const float4* __restrict__ wk, const float4* __restrict__ wv) {
    int z = blockIdx.z;
    const float4* x = (z == 0) ? hid : (z == 1) ? wq : (z == 2) ? wk : wv;
    int n4 = (z == 0) ? 1048576 : 262144;
    float m = 0.f;
    for (int i = blockIdx.x * blockDim.x + threadIdx.x; i < n4; i += gridDim.x * blockDim.x) {
        float4 v = x[i];
        m = fmaxf(m, fmaxf(fmaxf(fabsf(v.x), fabsf(v.y)), fmaxf(fabsf(v.z), fabsf(v.w))));
    }
#pragma unroll
    for (int o = 16; o > 0; o >>= 1) m = fmaxf(m, __shfl_xor_sync(0xffffffffu, m, o));
    if ((threadIdx.x & 31) == 0) atomicMax(&g_absmax[z], __float_as_uint(m));
}

__device__ __forceinline__ int pack4i(float a, float b, float c, float d) {
    int ia = (int)a, ib = (int)b, ic = (int)c, id = (int)d;
    return (ia & 0xFF) | ((ib & 0xFF) << 8) | ((ic & 0xFF) << 16) | ((id & 0xFF) << 24);
}

// all packing in one launch: z=0 act (q8 + residual), z=1..3 weights
__global__ void pack_all_k(const float4* __restrict__ hid, const float4* __restrict__ wq,
                           const float4* __restrict__ wk, const float4* __restrict__ wv,
                           int* __restrict__ q8, int* __restrict__ r8,
                           int* __restrict__ yq, int* __restrict__ yk, int* __restrict__ yv) {
    int z = blockIdx.z;
    if (z == 0) {
        float s  = fmaxf(__uint_as_float(g_absmax[0]), 1e-8f) / 127.0f;
        float s2 = s / 254.0f;
        for (int i = blockIdx.x * blockDim.x + threadIdx.x; i < 1048576;
             i += gridDim.x * blockDim.x) {
            float4 v = hid[i];
            float qa = fminf(fmaxf(rintf(v.x / s), -127.f), 127.f);
            float qb = fminf(fmaxf(rintf(v.y / s), -127.f), 127.f);
            float qc = fminf(fmaxf(rintf(v.z / s), -127.f), 127.f);
            float qd = fminf(fmaxf(rintf(v.w / s), -127.f), 127.f);
            q8[i] = pack4i(qa, qb, qc, qd);
            float ra = fminf(fmaxf(rintf((v.x - qa * s) / s2), -127.f), 127.f);
            float rb = fminf(fmaxf(rintf((v.y - qb * s) / s2), -127.f), 127.f);
            float rc = fminf(fmaxf(rintf((v.z - qc * s) / s2), -127.f), 127.f);
            float rd = fminf(fmaxf(rintf((v.w - qd * s) / s2), -127.f), 127.f);
            r8[i] = pack4i(ra, rb, rc, rd);
        }
    } else {
        const float4* x = (z == 1) ? wq : (z == 2) ? wk : wv;
        int* y = (z == 1) ? yq : (z == 2) ? yk : yv;
        float s = fmaxf(__uint_as_float(g_absmax[z]), 1e-8f) / 7.0f;
        for (int i = blockIdx.x * blockDim.x + threadIdx.x; i < 262144;
             i += gridDim.x * blockDim.x) {
            float4 v = x[i];
            float a = fminf(fmaxf(rintf(v.x / s), -7.f), 7.f);
            float b = fminf(fmaxf(rintf(v.y / s), -7.f), 7.f);
            float c = fminf(fmaxf(rintf(v.z / s), -7.f), 7.f);
            float d = fminf(fmaxf(rintf(v.w / s), -7.f), 7.f);
            y[i] = pack4i(a, b, c, d);
        }
    }
}

// fp32 -> packed {half hi, half lo}; x == hi + lo to ~2^-22 relative
__device__ __forceinline__ unsigned pack_f2h(float x) {
    __half h = __float2half_rn(x);
    __half l = __float2half_rn(x - __half2float(h));
    return (unsigned)__half_as_ushort(h) | ((unsigned)__half_as_ushort(l) << 16);
}

// ---------------- IMMA int8 tensor-core GEMM --------------------------------
__device__ __forceinline__ void imma16832(int& c0, int& c1, int& c2, int& c3,
                                          int a0, int a1, int a2, int a3,
                                          int b0, int b1) {
    asm volatile(
        "mma.sync.aligned.m16n8k32.row.col.s32.s8.s8.s32 "
        "{%0,%1,%2,%3},{%4,%5,%6,%7},{%8,%9},{%0,%1,%2,%3};"
        : "+r"(c0), "+r"(c1), "+r"(c2), "+r"(c3)
        : "r"(a0), "r"(a1), "r"(a2), "r"(a3), "r"(b0), "r"(b1));
}

__device__ __forceinline__ unsigned out_idx(int m, int n) {
    int bb = m >> 10, s = m & 1023, h = n >> 6, dh = n & 63;
    return (unsigned)(((bb * 16 + h) << 16) + (s << 6) + dh);
}

// C[m,n] = sum_d A[m,d]*W[n,d]; 128x128 tile, K=1024 int8 (256 int32/row).
// 256 threads = 8 warps (2m x 4n), warp tile 64x32.
// z=0: Q = hq8 @ Wq;  z=1: K = hq8 @ Wk;  z=2: V = (hq8, r8) @ Wv combined.
// smem rows stride 20 words (16-word slab + pad 4): conflict-free frag LDS.
__global__ __launch_bounds__(256) void gemm_all(
    const int* __restrict__ A8, const int* __restrict__ R8,
    const int* __restrict__ wq8, const int* __restrict__ wk8, const int* __restrict__ wv8,
    unsigned* __restrict__ Qo, unsigned* __restrict__ Ko, unsigned* __restrict__ Vo)
{
    __shared__ int As[128 * 20];
    __shared__ int Bs[128 * 20];
    __shared__ int Rs[128 * 20];

    int z = blockIdx.z;
    bool isv = (z == 2);
    const int* W = (z == 0) ? wq8 : (z == 1) ? wk8 : wv8;

    int tid = threadIdx.x;
    int m0 = blockIdx.y * 128, n0 = blockIdx.x * 128;
    int w = tid >> 5, lane = tid & 31, g = lane >> 2, t = lane & 3;
    int wm = (w >> 2) * 64, wn = (w & 3) * 32;

    int acc1[4][4][4];
    int acc2[4][4][4];
#pragma unroll
    for (int mi = 0; mi < 4; mi++)
#pragma unroll
        for (int ni = 0; ni < 4; ni++)
#pragma unroll
            for (int e = 0; e < 4; e++) { acc1[mi][ni][e] = 0; acc2[mi][ni][e] = 0; }

    int srow = tid >> 1, shalf = (tid & 1) * 8;
    const int* Ag = A8 + (m0 + srow) * 256 + shalf;
    const int* Rg = R8 + (m0 + srow) * 256 + shalf;
    const int* Wg = W  + (n0 + srow) * 256 + shalf;
    int sbase = srow * 20 + shalf;

    for (int ks = 0; ks < 16; ks++) {
        int4 av0 = *(const int4*)(Ag + ks * 16);
        int4 av1 = *(const int4*)(Ag + ks * 16 + 4);
        int4 bv0 = *(const int4*)(Wg + ks * 16);
        int4 bv1 = *(const int4*)(Wg + ks * 16 + 4);
        *(int4*)&As[sbase]     = av0;
        *(int4*)&As[sbase + 4] = av1;
        *(int4*)&Bs[sbase]     = bv0;
        *(int4*)&Bs[sbase + 4] = bv1;
        if (isv) {
            int4 rv0 = *(const int4*)(Rg + ks * 16);
            int4 rv1 = *(const int4*)(Rg + ks * 16 + 4);
            *(int4*)&Rs[sbase]     = rv0;
            *(int4*)&Rs[sbase + 4] = rv1;
        }
        __syncthreads();

#pragma unroll
        for (int kk = 0; kk < 2; kk++) {
            int bb0[4], bb1[4];
#pragma unroll
            for (int ni = 0; ni < 4; ni++) {
                int brow = (wn + ni * 8 + g) * 20 + kk * 8;
                bb0[ni] = Bs[brow + t];
                bb1[ni] = Bs[brow + 4 + t];
            }
#pragma unroll
            for (int mi = 0; mi < 4; mi++) {
                int ar0 = (wm + mi * 16 + g) * 20 + kk * 8;
                int ar1 = (wm + mi * 16 + 8 + g) * 20 + kk * 8;
                int a0 = As[ar0 + t], a1 = As[ar1 + t];
                int a2 = As[ar0 + 4 + t], a3 = As[ar1 + 4 + t];
#pragma unroll
                for (int ni = 0; ni < 4; ni++)
                    imma16832(acc1[mi][ni][0], acc1[mi][ni][1], acc1[mi][ni][2], acc1[mi][ni][3],
                              a0, a1, a2, a3, bb0[ni], bb1[ni]);
                if (isv) {
                    int r0 = Rs[ar0 + t], r1 = Rs[ar1 + t];
                    int r2 = Rs[ar0 + 4 + t], r3 = Rs[ar1 + 4 + t];
#pragma unroll
                    for (int ni = 0; ni < 4; ni++)
                        imma16832(acc2[mi][ni][0], acc2[mi][ni][1], acc2[mi][ni][2], acc2[mi][ni][3],
                                  r0, r1, r2, r3, bb0[ni], bb1[ni]);
                }
            }
        }
        __syncthreads();
    }

    float sa = fmaxf(__uint_as_float(g_absmax[0]), 1e-8f) / 127.0f;
    float sw = fmaxf(__uint_as_float(g_absmax[z + 1]), 1e-8f) / 7.0f;
    float k1 = sa * sw;
    float k2 = (sa / 254.0f) * sw;
    unsigned* O = (z == 0) ? Qo : (z == 1) ? Ko : Vo;

#pragma unroll
    for (int mi = 0; mi < 4; mi++) {
        int r0 = m0 + wm + mi * 16 + g;
        int r1 = r0 + 8;
#pragma unroll
        for (int ni = 0; ni < 4; ni++) {
            int c0 = n0 + wn + ni * 8 + 2 * t;
            if (!isv) {
                O[out_idx(r0, c0)]     = pack_f2h((float)acc1[mi][ni][0] * k1);
                O[out_idx(r0, c0 + 1)] = pack_f2h((float)acc1[mi][ni][1] * k1);
                O[out_idx(r1, c0)]     = pack_f2h((float)acc1[mi][ni][2] * k1);
                O[out_idx(r1, c0 + 1)] = pack_f2h((float)acc1[mi][ni][3] * k1);
            } else {
                O[out_idx(r0, c0)]     = pack_f2h(fmaf((float)acc2[mi][ni][0], k2, (float)acc1[mi][ni][0] * k1));
                O[out_idx(r0, c0 + 1)] = pack_f2h(fmaf((float)acc2[mi][ni][1], k2, (float)acc1[mi][ni][1] * k1));
                O[out_idx(r1, c0)]     = pack_f2h(fmaf((float)acc2[mi][ni][2], k2, (float)acc1[mi][ni][2] * k1));
                O[out_idx(r1, c0 + 1)] = pack_f2h(fmaf((float)acc2[mi][ni][3], k2, (float)acc1[mi][ni][3] * k1));
            }
        }
    }
}

// ---------------- JAX threefry2x32 noise (partitionable, key=(0,42)) --------
__device__ __forceinline__ uint32_t rotl32(uint32_t x, int r) {
    return (x << r) | (x >> (32 - r));
}

__device__ __forceinline__ void threefry2x32(uint32_t c0, uint32_t c1,
                                             uint32_t& o0, uint32_t& o1) {
    const uint32_t k0 = 0u, k1 = 42u, k2 = 0u ^ 42u ^ 0x1BD11BDAu;
    uint32_t x0 = c0 + k0, x1 = c1 + k1;
#define TF_R(r) { x0 += x1; x1 = rotl32(x1, r); x1 ^= x0; }
    TF_R(13) TF_R(15) TF_R(26) TF_R(6)
    x0 += k1; x1 += k2 + 1u;
    TF_R(17) TF_R(29) TF_R(16) TF_R(24)
    x0 += k2; x1 += k0 + 2u;
    TF_R(13) TF_R(15) TF_R(26) TF_R(6)
    x0 += k0; x1 += k1 + 3u;
    TF_R(17) TF_R(29) TF_R(16) TF_R(24)
    x0 += k1; x1 += k2 + 4u;
    TF_R(13) TF_R(15) TF_R(26) TF_R(6)
    x0 += k2; x1 += k0 + 5u;
#undef TF_R
    o0 = x0; o1 = x1;
}

__device__ __forceinline__ float noise_at(unsigned int i) {
    uint32_t o0, o1;
    threefry2x32(0u, i, o0, o1);
    uint32_t bits = o0 ^ o1;
    float f = __uint_as_float((bits >> 9) | 0x3f800000u) - 1.0f;
    const float lo = -0.99999994f;
    float u = fmaxf(lo, fmaf(f, 2.0f, lo));
    float t = fmaf(-u, u, 1.0f);
    float w = -__logf(t);
    float p;
    if (w < 5.0f) {
        w = w - 2.5f;
        p = 2.81022636e-08f;
        p = fmaf(p, w, 3.43273939e-07f);
        p = fmaf(p, w, -3.5233877e-06f);
        p = fmaf(p, w, -4.39150654e-06f);
        p = fmaf(p, w, 0.00021858087f);
        p = fmaf(p, w, -0.00125372503f);
        p = fmaf(p, w, -0.00417768164f);
        p = fmaf(p, w, 0.246640727f);
        p = fmaf(p, w, 1.50140941f);
    } else {
        w = sqrtf(w) - 3.0f;
        p = -0.000200214257f;
        p = fmaf(p, w, 0.000100950558f);
        p = fmaf(p, w, 0.00134934322f);
        p = fmaf(p, w, -0.00367342844f);
        p = fmaf(p, w, 0.00573950773f);
        p = fmaf(p, w, -0.0076224613f);
        p = fmaf(p, w, 0.00943887047f);
        p = fmaf(p, w, 1.00167406f);
        p = fmaf(p, w, 2.83297682f);
    }
    return 1.41421356f * (p * u) * 0.05f;
}

// ---------------- HMMA helpers ----------------------------------------------
__device__ __forceinline__ void mma16816(float& c0, float& c1, float& c2, float& c3,
                                         unsigned a0, unsigned a1, unsigned a2, unsigned a3,
                                         unsigned b0, unsigned b1) {
    asm volatile(
        "mma.sync.aligned.m16n8k16.row.col.f32.f16.f16.f32 "
        "{%0,%1,%2,%3},{%4,%5,%6,%7},{%8,%9},{%0,%1,%2,%3};"
        : "+f"(c0), "+f"(c1), "+f"(c2), "+f"(c3)
        : "r"(a0), "r"(a1), "r"(a2), "r"(a3), "r"(b0), "r"(b1));
}

__device__ __forceinline__ unsigned h2pack(float x, float y) {
    __half2 h = __float22half2_rn(make_float2(x, y));
    return *(unsigned*)&h;
}

// ---------------- fused flash attention (HMMA, hi/lo fp16 split) -------------
// grid (64 bh, 16 qt); 128 threads = 4 warps; warp w owns q rows [w*16, w*16+16).
// Planes stored as 32-bit words (two adjacent halves packed). Row stride 36 words.
// V planes are [dh][k-word] with XOR swizzle col = kp ^ ((dh>>3)&3) -> conflict-free.
#define PLANEW 2304   // 64 rows * 36 words
__global__ __launch_bounds__(128, 3) void attn_k(
    const unsigned* __restrict__ Q, const unsigned* __restrict__ K,
    const unsigned* __restrict__ V, const float* __restrict__ mask,
    float* __restrict__ out)
{
    extern __shared__ unsigned smw[];
    unsigned* qhi = smw;
    unsigned* qlo = smw + PLANEW;
    unsigned* khi = smw + 2 * PLANEW;
    unsigned* klo = smw + 3 * PLANEW;
    unsigned* vhi = smw + 4 * PLANEW;
    unsigned* vlo = smw + 5 * PLANEW;
    float* Ms = (float*)(smw + 6 * PLANEW);

    int bh = blockIdx.x, qt = blockIdx.y;
    int b = bh >> 4, h = bh & 15;
    int tid = threadIdx.x, w = tid >> 5, lane = tid & 31;
    int g = lane >> 2, t = lane & 3;

    // ---- load Q tile: split packed {hi,lo} into word planes (4B stores)
    const unsigned* Qg = Q + (bh * 1024 + qt * 64) * 64;
    for (int i = tid; i < 2048; i += 128) {
        int q = i >> 5, dp = i & 31;
        uint2 u = *(const uint2*)&Qg[q * 64 + 2 * dp];
        qhi[q * 36 + dp] = __byte_perm(u.x, u.y, 0x5410);
        qlo[q * 36 + dp] = __byte_perm(u.x, u.y, 0x7632);
    }
    __syncthreads();

    // ---- Q A-fragments in registers
    unsigned qh[4][4], ql[4][4];
    int qr = w * 16 + g;
#pragma unroll
    for (int c = 0; c < 4; c++) {
        int wp = c * 8 + t;
        qh[c][0] = qhi[qr * 36 + wp];
        qh[c][1] = qhi[(qr + 8) * 36 + wp];
        qh[c][2] = qhi[qr * 36 + wp + 4];
        qh[c][3] = qhi[(qr + 8) * 36 + wp + 4];
        ql[c][0] = qlo[qr * 36 + wp];
        ql[c][1] = qlo[(qr + 8) * 36 + wp];
        ql[c][2] = qlo[qr * 36 + wp + 4];
        ql[c][3] = qlo[(qr + 8) * 36 + wp + 4];
    }

    float m0r = -1e30f, m1r = -1e30f, l0r = 0.f, l1r = 0.f;
    float O[8][4];
#pragma unroll
    for (int n = 0; n < 8; n++)
#pragma unroll
        for (int e = 0; e < 4; e++) O[n][e] = 0.f;

    const float* maskb = mask + (b << 10);
    unsigned base0 = ((unsigned)bh << 20) | ((unsigned)(qt * 64 + qr) << 10);

    for (int kt = 0; kt < 16; kt++) {
        __syncthreads();
        const unsigned* Kg = K + (bh * 1024 + kt * 64) * 64;
        const unsigned* Vg = V + (bh * 1024 + kt * 64) * 64;
        for (int i = tid; i < 2048; i += 128) {
            // K planes: [k][d-word], conflict-free
            int k = i >> 5, dp = i & 31;
            uint2 u = *(const uint2*)&Kg[k * 64 + 2 * dp];
            khi[k * 36 + dp] = __byte_perm(u.x, u.y, 0x5410);
            klo[k * 36 + dp] = __byte_perm(u.x, u.y, 0x7632);
            // V planes transposed: [dh][k-word], XOR swizzle for conflict-free writes
            int d = i & 63, kp = i >> 6;
            unsigned v0 = Vg[(2 * kp) * 64 + d];
            unsigned v1 = Vg[(2 * kp + 1) * 64 + d];
            int col = kp ^ ((d >> 3) & 3);
            vhi[d * 36 + col] = __byte_perm(v0, v1, 0x5410);
            vlo[d * 36 + col] = __byte_perm(v0, v1, 0x7632);
        }
        if (tid < 64) Ms[tid] = maskb[kt * 64 + tid];
        __syncthreads();

        // ---- S = Q K^T (3-term hi/lo split)
        float S[8][4];
#pragma unroll
        for (int n = 0; n < 8; n++)
#pragma unroll
            for (int e = 0; e < 4; e++) S[n][e] = 0.f;

#pragma unroll
        for (int j = 0; j < 8; j++) {
            int krow = j * 8 + g;
#pragma unroll
            for (int c = 0; c < 4; c++) {
                int wp = c * 8 + t;
                unsigned bh0 = khi[krow * 36 + wp];
                unsigned bh1 = khi[krow * 36 + wp + 4];
                unsigned bl0 = klo[krow * 36 + wp];
                unsigned bl1 = klo[krow * 36 + wp + 4];
                mma16816(S[j][0], S[j][1], S[j][2], S[j][3],
                         qh[c][0], qh[c][1], qh[c][2], qh[c][3], bh0, bh1);
                mma16816(S[j][0], S[j][1], S[j][2], S[j][3],
                         qh[c][0], qh[c][1], qh[c][2], qh[c][3], bl0, bl1);
                mma16816(S[j][0], S[j][1], S[j][2], S[j][3],
                         ql[c][0], ql[c][1], ql[c][2], ql[c][3], bh0, bh1);
            }
        }

        // ---- scale + noise + mask
#pragma unroll
        for (int j = 0; j < 8; j++) {
            unsigned kc = (unsigned)(kt * 64 + j * 8 + 2 * t);
            float mv0 = Ms[j * 8 + 2 * t], mv1 = Ms[j * 8 + 2 * t + 1];
            S[j][0] = fmaf(S[j][0], 0.125f, noise_at(base0 + kc) + mv0);
            S[j][1] = fmaf(S[j][1], 0.125f, noise_at(base0 + kc + 1) + mv1);
            S[j][2] = fmaf(S[j][2], 0.125f, noise_at(base0 + (8u << 10) + kc) + mv0);
            S[j][3] = fmaf(S[j][3], 0.125f, noise_at(base0 + (8u << 10) + kc + 1) + mv1);
        }

        // ---- online softmax (rows qr and qr+8; reduce over quad lanes)
        float tm0 = -1e30f, tm1 = -1e30f;
#pragma unroll
        for (int j = 0; j < 8; j++) {
            tm0 = fmaxf(tm0, fmaxf(S[j][0], S[j][1]));
            tm1 = fmaxf(tm1, fmaxf(S[j][2], S[j][3]));
        }
        tm0 = fmaxf(tm0, __shfl_xor_sync(0xffffffffu, tm0, 1));
        tm0 = fmaxf(tm0, __shfl_xor_sync(0xffffffffu, tm0, 2));
        tm1 = fmaxf(tm1, __shfl_xor_sync(0xffffffffu, tm1, 1));
        tm1 = fmaxf(tm1, __shfl_xor_sync(0xffffffffu, tm1, 2));
        float mn0 = fmaxf(m0r, tm0), mn1 = fmaxf(m1r, tm1);
        float cor0 = __expf(m0r - mn0), cor1 = __expf(m1r - mn1);
        m0r = mn0; m1r = mn1;
        float ps0 = 0.f, ps1 = 0.f;
#pragma unroll
        for (int j = 0; j < 8; j++) {
            S[j][0] = __expf(S[j][0] - mn0); S[j][1] = __expf(S[j][1] - mn0);
            S[j][2] = __expf(S[j][2] - mn1); S[j][3] = __expf(S[j][3] - mn1);
            ps0 += S[j][0] + S[j][1];
            ps1 += S[j][2] + S[j][3];
        }
        ps0 += __shfl_xor_sync(0xffffffffu, ps0, 1);
        ps0 += __shfl_xor_sync(0xffffffffu, ps0, 2);
        ps1 += __shfl_xor_sync(0xffffffffu, ps1, 1);
        ps1 += __shfl_xor_sync(0xffffffffu, ps1, 2);
        l0r = l0r * cor0 + ps0;
        l1r = l1r * cor1 + ps1;
#pragma unroll
        for (int n = 0; n < 8; n++) {
            O[n][0] *= cor0; O[n][1] *= cor0;
            O[n][2] *= cor1; O[n][3] *= cor1;
        }

        // ---- P C-frags -> A-frags (register-only), hi/lo split
        unsigned ph[4][4], pl[4][4];
#pragma unroll
        for (int c = 0; c < 4; c++) {
            float v0 = S[2 * c][0],     v1 = S[2 * c][1];
            float v2 = S[2 * c][2],     v3 = S[2 * c][3];
            float v4 = S[2 * c + 1][0], v5 = S[2 * c + 1][1];
            float v6 = S[2 * c + 1][2], v7 = S[2 * c + 1][3];
            ph[c][0] = h2pack(v0, v1);
            ph[c][1] = h2pack(v2, v3);
            ph[c][2] = h2pack(v4, v5);
            ph[c][3] = h2pack(v6, v7);
            __half2* hp;
            hp = (__half2*)&ph[c][0];
            pl[c][0] = h2pack(v0 - __half2float(hp->x), v1 - __half2float(hp->y));
            hp = (__half2*)&ph[c][1];
            pl[c][1] = h2pack(v2 - __half2float(hp->x), v3 - __half2float(hp->y));
            hp = (__half2*)&ph[c][2];
            pl[c][2] = h2pack(v4 - __half2float(hp->x), v5 - __half2float(hp->y));
            hp = (__half2*)&ph[c][3];
            pl[c][3] = h2pack(v6 - __half2float(hp->x), v7 - __half2float(hp->y));
        }

        // ---- O += P V (3-term hi/lo split); swizzled V^T planes give B-frags
#pragma unroll
        for (int n = 0; n < 8; n++) {
            int vrow = n * 8 + g;
            int vs = n & 3;
#pragma unroll
            for (int c = 0; c < 4; c++) {
                int wp0 = (c * 8 + t) ^ vs;
                int wp1 = (c * 8 + 4 + t) ^ vs;
                unsigned bh0 = vhi[vrow * 36 + wp0];
                unsigned bh1 = vhi[vrow * 36 + wp1];
                unsigned bl0 = vlo[vrow * 36 + wp0];
                unsigned bl1 = vlo[vrow * 36 + wp1];
                mma16816(O[n][0], O[n][1], O[n][2], O[n][3],
                         ph[c][0], ph[c][1], ph[c][2], ph[c][3], bh0, bh1);
                mma16816(O[n][0], O[n][1], O[n][2], O[n][3],
                         ph[c][0], ph[c][1], ph[c][2], ph[c][3], bl0, bl1);
                mma16816(O[n][0], O[n][1], O[n][2], O[n][3],
                         pl[c][0], pl[c][1], pl[c][2], pl[c][3], bh0, bh1);
            }
        }
    }

    // ---- epilogue
    float inv0 = 1.0f / l0r, inv1 = 1.0f / l1r;
    int q0 = qt * 64 + qr;
    float* o0 = out + ((size_t)((b << 10) + q0)) * 1024 + (h << 6);
    float* o1 = out + ((size_t)((b << 10) + q0 + 8)) * 1024 + (h << 6);
#pragma unroll
    for (int n = 0; n < 8; n++) {
        int dh = n * 8 + 2 * t;
        *(float2*)(o0 + dh) = make_float2(O[n][0] * inv0, O[n][1] * inv0);
        *(float2*)(o1 + dh) = make_float2(O[n][2] * inv1, O[n][3] * inv1);
    }
}

// ---------------- launch -----------------------------------------------------
extern "C" void kernel_launch(void* const* d_in, const int* in_sizes, int n_in,
                              void* d_out, int out_size) {
    const float* hidden = (const float*)d_in[0];
    const float* mask   = (const float*)d_in[1];
    const float* Wq     = (const float*)d_in[2];
    const float* Wk     = (const float*)d_in[3];
    const float* Wv     = (const float*)d_in[4];
    float* out = (float*)d_out;

    int *hq8, *r8, *wq8, *wk8, *wv8;
    unsigned *Qp, *Kp, *Vp;
    cudaGetSymbolAddress((void**)&hq8, g_hq8);
    cudaGetSymbolAddress((void**)&r8,  g_r8);
    cudaGetSymbolAddress((void**)&wq8, g_wq8);
    cudaGetSymbolAddress((void**)&wk8, g_wk8);
    cudaGetSymbolAddress((void**)&wv8, g_wv8);
    cudaGetSymbolAddress((void**)&Qp,  g_Qh);
    cudaGetSymbolAddress((void**)&Kp,  g_Kh);
    cudaGetSymbolAddress((void**)&Vp,  g_Vh);

    init_k<<<1, 32>>>();
    absmax_all_k<<<dim3(128, 1, 4), 256>>>((const float4*)hidden, (const float4*)Wq,
                                           (const float4*)Wk, (const float4*)Wv);
    pack_all_k<<<dim3(256, 1, 4), 256>>>((const float4*)hidden, (const float4*)Wq,
                                         (const float4*)Wk, (const float4*)Wv,
                                         hq8, r8, wq8, wk8, wv8);
    gemm_all<<<dim3(8, 32, 3), 256>>>(hq8, r8, wq8, wk8, wv8, Qp, Kp, Vp);

    int smem_bytes = 6 * PLANEW * 4 + 64 * 4;   // 6 word planes + mask
    cudaFuncSetAttribute(attn_k, cudaFuncAttributeMaxDynamicSharedMemorySize, smem_bytes);
    attn_k<<<dim3(64, 16), 128, smem_bytes>>>(Qp, Kp, Vp, mask, out);
}

// round 11
// speedup vs baseline: 1.2015x; 1.0430x over previous
#include <cuda_runtime.h>
#include <cuda_fp16.h>
#include <cstdint>

// ---------------- scratch (__device__ globals; no allocs allowed) ------------
__device__ int      g_hq8[1048576];   // hidden quantized int8, packed 4/int32
__device__ int      g_r8 [1048576];   // residual quantized int8, packed
__device__ int      g_wq8[262144];
__device__ int      g_wk8[262144];
__device__ int      g_wv8[262144];
__device__ unsigned g_Qh[4194304];    // [B*H, S, 64] packed {fp16 hi, fp16 lo}
__device__ unsigned g_Kh[4194304];
__device__ unsigned g_Vh[4194304];
__device__ unsigned int g_absmax[4];  // 0:hidden 1:Wq 2:Wk 3:Wv

// ---------------- absmax / packing ------------------------------------------
__global__ void init_k() {
    if (threadIdx.x < 4) g_absmax[threadIdx.x] = 0u;
}

__global__ void absmax_all_k(const float4* __restrict__ hid, const float4* __restrict__ wq,
                             const float4* __restrict__ wk, const float4* __restrict__ wv) {
    int z = blockIdx.z;
    const float4* x = (z == 0) ? hid : (z == 1) ? wq : (z == 2) ? wk : wv;
    int n4 = (z == 0) ? 1048576 : 262144;
    float m = 0.f;
    for (int i = blockIdx.x * blockDim.x + threadIdx.x; i < n4; i += gridDim.x * blockDim.x) {
        float4 v = x[i];
        m = fmaxf(m, fmaxf(fmaxf(fabsf(v.x), fabsf(v.y)), fmaxf(fabsf(v.z), fabsf(v.w))));
    }
#pragma unroll
    for (int o = 16; o > 0; o >>= 1) m = fmaxf(m, __shfl_xor_sync(0xffffffffu, m, o));
    if ((threadIdx.x & 31) == 0) atomicMax(&g_absmax[z], __float_as_uint(m));
}

__device__ __forceinline__ int pack4i(float a, float b, float c, float d) {
    int ia = (int)a, ib = (int)b, ic = (int)c, id = (int)d;
    return (ia & 0xFF) | ((ib & 0xFF) << 8) | ((ic & 0xFF) << 16) | ((id & 0xFF) << 24);
}

__global__ void pack_all_k(const float4* __restrict__ hid, const float4* __restrict__ wq,
                           const float4* __restrict__ wk, const float4* __restrict__ wv,
                           int* __restrict__ q8, int* __restrict__ r8,
                           int* __restrict__ yq, int* __restrict__ yk, int* __restrict__ yv) {
    int z = blockIdx.z;
    if (z == 0) {
        float s  = fmaxf(__uint_as_float(g_absmax[0]), 1e-8f) / 127.0f;
        float s2 = s / 254.0f;
        for (int i = blockIdx.x * blockDim.x + threadIdx.x; i < 1048576;
             i += gridDim.x * blockDim.x) {
            float4 v = hid[i];
            float qa = fminf(fmaxf(rintf(v.x / s), -127.f), 127.f);
            float qb = fminf(fmaxf(rintf(v.y / s), -127.f), 127.f);
            float qc = fminf(fmaxf(rintf(v.z / s), -127.f), 127.f);
            float qd = fminf(fmaxf(rintf(v.w / s), -127.f), 127.f);
            q8[i] = pack4i(qa, qb, qc, qd);
            float ra = fminf(fmaxf(rintf((v.x - qa * s) / s2), -127.f), 127.f);
            float rb = fminf(fmaxf(rintf((v.y - qb * s) / s2), -127.f), 127.f);
            float rc = fminf(fmaxf(rintf((v.z - qc * s) / s2), -127.f), 127.f);
            float rd = fminf(fmaxf(rintf((v.w - qd * s) / s2), -127.f), 127.f);
            r8[i] = pack4i(ra, rb, rc, rd);
        }
    } else {
        const float4* x = (z == 1) ? wq : (z == 2) ? wk : wv;
        int* y = (z == 1) ? yq : (z == 2) ? yk : yv;
        float s = fmaxf(__uint_as_float(g_absmax[z]), 1e-8f) / 7.0f;
        for (int i = blockIdx.x * blockDim.x + threadIdx.x; i < 262144;
             i += gridDim.x * blockDim.x) {
            float4 v = x[i];
            float a = fminf(fmaxf(rintf(v.x / s), -7.f), 7.f);
            float b = fminf(fmaxf(rintf(v.y / s), -7.f), 7.f);
            float c = fminf(fmaxf(rintf(v.z / s), -7.f), 7.f);
            float d = fminf(fmaxf(rintf(v.w / s), -7.f), 7.f);
            y[i] = pack4i(a, b, c, d);
        }
    }
}

// fp32 -> packed {half hi, half lo}; x == hi + lo to ~2^-22 relative
__device__ __forceinline__ unsigned pack_f2h(float x) {
    __half h = __float2half_rn(x);
    __half l = __float2half_rn(x - __half2float(h));
    return (unsigned)__half_as_ushort(h) | ((unsigned)__half_as_ushort(l) << 16);
}

// ---------------- IMMA int8 tensor-core GEMM --------------------------------
__device__ __forceinline__ void imma16832(int& c0, int& c1, int& c2, int& c3,
                                          int a0, int a1, int a2, int a3,
                                          int b0, int b1) {
    asm volatile(
        "mma.sync.aligned.m16n8k32.row.col.s32.s8.s8.s32 "
        "{%0,%1,%2,%3},{%4,%5,%6,%7},{%8,%9},{%0,%1,%2,%3};"
        : "+r"(c0), "+r"(c1), "+r"(c2), "+r"(c3)
        : "r"(a0), "r"(a1), "r"(a2), "r"(a3), "r"(b0), "r"(b1));
}

__device__ __forceinline__ unsigned out_idx(int m, int n) {
    int bb = m >> 10, s = m & 1023, h = n >> 6, dh = n & 63;
    return (unsigned)(((bb * 16 + h) << 16) + (s << 6) + dh);
}

// C[m,n] = sum_d A[m,d]*W[n,d]; 128x128 tile, K=1024 int8 (256 int32/row).
// 256 threads = 8 warps (2m x 4n), warp tile 64x32.
// ISV=0: Q/K (z selects weight; acc1 only -> 2 blocks/SM).
// ISV=1: V = (hq8, r8) @ Wv combined (acc1+acc2 -> 1 block/SM).
template <int ISV>
__global__ __launch_bounds__(256, ISV ? 1 : 2) void gemm_imma(
    const int* __restrict__ A8, const int* __restrict__ R8,
    const int* __restrict__ wq8, const int* __restrict__ wk8, const int* __restrict__ wv8,
    unsigned* __restrict__ Qo, unsigned* __restrict__ Ko, unsigned* __restrict__ Vo)
{
    __shared__ int As[128 * 20];
    __shared__ int Bs[128 * 20];
    __shared__ int Rs[ISV ? 128 * 20 : 1];

    int z = ISV ? 2 : blockIdx.z;
    const int* W = (z == 0) ? wq8 : (z == 1) ? wk8 : wv8;

    int tid = threadIdx.x;
    int m0 = blockIdx.y * 128, n0 = blockIdx.x * 128;
    int w = tid >> 5, lane = tid & 31, g = lane >> 2, t = lane & 3;
    int wm = (w >> 2) * 64, wn = (w & 3) * 32;

    int acc1[4][4][4];
    int acc2[ISV ? 4 : 1][ISV ? 4 : 1][4];
#pragma unroll
    for (int mi = 0; mi < 4; mi++)
#pragma unroll
        for (int ni = 0; ni < 4; ni++)
#pragma unroll
            for (int e = 0; e < 4; e++) acc1[mi][ni][e] = 0;
    if (ISV) {
#pragma unroll
        for (int mi = 0; mi < 4; mi++)
#pragma unroll
            for (int ni = 0; ni < 4; ni++)
#pragma unroll
                for (int e = 0; e < 4; e++) acc2[mi][ni][e] = 0;
    }

    int srow = tid >> 1, shalf = (tid & 1) * 8;
    const int* Ag = A8 + (m0 + srow) * 256 + shalf;
    const int* Rg = R8 + (m0 + srow) * 256 + shalf;
    const int* Wg = W  + (n0 + srow) * 256 + shalf;
    int sbase = srow * 20 + shalf;

    for (int ks = 0; ks < 16; ks++) {
        int4 av0 = *(const int4*)(Ag + ks * 16);
        int4 av1 = *(const int4*)(Ag + ks * 16 + 4);
        int4 bv0 = *(const int4*)(Wg + ks * 16);
        int4 bv1 = *(const int4*)(Wg + ks * 16 + 4);
        *(int4*)&As[sbase]     = av0;
        *(int4*)&As[sbase + 4] = av1;
        *(int4*)&Bs[sbase]     = bv0;
        *(int4*)&Bs[sbase + 4] = bv1;
        if (ISV) {
            int4 rv0 = *(const int4*)(Rg + ks * 16);
            int4 rv1 = *(const int4*)(Rg + ks * 16 + 4);
            *(int4*)&Rs[sbase]     = rv0;
            *(int4*)&Rs[sbase + 4] = rv1;
        }
        __syncthreads();

#pragma unroll
        for (int kk = 0; kk < 2; kk++) {
            int bb0[4], bb1[4];
#pragma unroll
            for (int ni = 0; ni < 4; ni++) {
                int brow = (wn + ni * 8 + g) * 20 + kk * 8;
                bb0[ni] = Bs[brow + t];
                bb1[ni] = Bs[brow + 4 + t];
            }
#pragma unroll
            for (int mi = 0; mi < 4; mi++) {
                int ar0 = (wm + mi * 16 + g) * 20 + kk * 8;
                int ar1 = (wm + mi * 16 + 8 + g) * 20 + kk * 8;
                int a0 = As[ar0 + t], a1 = As[ar1 + t];
                int a2 = As[ar0 + 4 + t], a3 = As[ar1 + 4 + t];
#pragma unroll
                for (int ni = 0; ni < 4; ni++)
                    imma16832(acc1[mi][ni][0], acc1[mi][ni][1], acc1[mi][ni][2], acc1[mi][ni][3],
                              a0, a1, a2, a3, bb0[ni], bb1[ni]);
                if (ISV) {
                    int r0 = Rs[ar0 + t], r1 = Rs[ar1 + t];
                    int r2 = Rs[ar0 + 4 + t], r3 = Rs[ar1 + 4 + t];
#pragma unroll
                    for (int ni = 0; ni < 4; ni++)
                        imma16832(acc2[mi][ni][0], acc2[mi][ni][1], acc2[mi][ni][2], acc2[mi][ni][3],
                                  r0, r1, r2, r3, bb0[ni], bb1[ni]);
                }
            }
        }
        __syncthreads();
    }

    float sa = fmaxf(__uint_as_float(g_absmax[0]), 1e-8f) / 127.0f;
    float sw = fmaxf(__uint_as_float(g_absmax[z + 1]), 1e-8f) / 7.0f;
    float k1 = sa * sw;
    float k2 = (sa / 254.0f) * sw;
    unsigned* O = (z == 0) ? Qo : (z == 1) ? Ko : Vo;

#pragma unroll
    for (int mi = 0; mi < 4; mi++) {
        int r0 = m0 + wm + mi * 16 + g;
        int r1 = r0 + 8;
#pragma unroll
        for (int ni = 0; ni < 4; ni++) {
            int c0 = n0 + wn + ni * 8 + 2 * t;
            if (!ISV) {
                O[out_idx(r0, c0)]     = pack_f2h((float)acc1[mi][ni][0] * k1);
                O[out_idx(r0, c0 + 1)] = pack_f2h((float)acc1[mi][ni][1] * k1);
                O[out_idx(r1, c0)]     = pack_f2h((float)acc1[mi][ni][2] * k1);
                O[out_idx(r1, c0 + 1)] = pack_f2h((float)acc1[mi][ni][3] * k1);
            } else {
                O[out_idx(r0, c0)]     = pack_f2h(fmaf((float)acc2[mi][ni][0], k2, (float)acc1[mi][ni][0] * k1));
                O[out_idx(r0, c0 + 1)] = pack_f2h(fmaf((float)acc2[mi][ni][1], k2, (float)acc1[mi][ni][1] * k1));
                O[out_idx(r1, c0)]     = pack_f2h(fmaf((float)acc2[mi][ni][2], k2, (float)acc1[mi][ni][2] * k1));
                O[out_idx(r1, c0 + 1)] = pack_f2h(fmaf((float)acc2[mi][ni][3], k2, (float)acc1[mi][ni][3] * k1));
            }
        }
    }
}

// ---------------- JAX threefry2x32 noise (partitionable, key=(0,42)) --------
__device__ __forceinline__ uint32_t rotl32(uint32_t x, int r) {
    return (x << r) | (x >> (32 - r));
}

__device__ __forceinline__ void threefry2x32(uint32_t c0, uint32_t c1,
                                             uint32_t& o0, uint32_t& o1) {
    const uint32_t k0 = 0u, k1 = 42u, k2 = 0u ^ 42u ^ 0x1BD11BDAu;
    uint32_t x0 = c0 + k0, x1 = c1 + k1;
#define TF_R(r) { x0 += x1; x1 = rotl32(x1, r); x1 ^= x0; }
    TF_R(13) TF_R(15) TF_R(26) TF_R(6)
    x0 += k1; x1 += k2 + 1u;
    TF_R(17) TF_R(29) TF_R(16) TF_R(24)
    x0 += k2; x1 += k0 + 2u;
    TF_R(13) TF_R(15) TF_R(26) TF_R(6)
    x0 += k0; x1 += k1 + 3u;
    TF_R(17) TF_R(29) TF_R(16) TF_R(24)
    x0 += k1; x1 += k2 + 4u;
    TF_R(13) TF_R(15) TF_R(26) TF_R(6)
    x0 += k2; x1 += k0 + 5u;
#undef TF_R
    o0 = x0; o1 = x1;
}

__device__ __forceinline__ float noise_at(unsigned int i) {
    uint32_t o0, o1;
    threefry2x32(0u, i, o0, o1);
    uint32_t bits = o0 ^ o1;
    float f = __uint_as_float((bits >> 9) | 0x3f800000u) - 1.0f;
    const float lo = -0.99999994f;
    float u = fmaxf(lo, fmaf(f, 2.0f, lo));
    float t = fmaf(-u, u, 1.0f);
    float w = -__logf(t);
    float p;
    if (w < 5.0f) {
        w = w - 2.5f;
        p = 2.81022636e-08f;
        p = fmaf(p, w, 3.43273939e-07f);
        p = fmaf(p, w, -3.5233877e-06f);
        p = fmaf(p, w, -4.39150654e-06f);
        p = fmaf(p, w, 0.00021858087f);
        p = fmaf(p, w, -0.00125372503f);
        p = fmaf(p, w, -0.00417768164f);
        p = fmaf(p, w, 0.246640727f);
        p = fmaf(p, w, 1.50140941f);
    } else {
        w = sqrtf(w) - 3.0f;
        p = -0.000200214257f;
        p = fmaf(p, w, 0.000100950558f);
        p = fmaf(p, w, 0.00134934322f);
        p = fmaf(p, w, -0.00367342844f);
        p = fmaf(p, w, 0.00573950773f);
        p = fmaf(p, w, -0.0076224613f);
        p = fmaf(p, w, 0.00943887047f);
        p = fmaf(p, w, 1.00167406f);
        p = fmaf(p, w, 2.83297682f);
    }
    return 1.41421356f * (p * u) * 0.05f;
}

// ---------------- HMMA helpers ----------------------------------------------
__device__ __forceinline__ void mma16816(float& c0, float& c1, float& c2, float& c3,
                                         unsigned a0, unsigned a1, unsigned a2, unsigned a3,
                                         unsigned b0, unsigned b1) {
    asm volatile(
        "mma.sync.aligned.m16n8k16.row.col.f32.f16.f16.f32 "
        "{%0,%1,%2,%3},{%4,%5,%6,%7},{%8,%9},{%0,%1,%2,%3};"
        : "+f"(c0), "+f"(c1), "+f"(c2), "+f"(c3)
        : "r"(a0), "r"(a1), "r"(a2), "r"(a3), "r"(b0), "r"(b1));
}

__device__ __forceinline__ unsigned h2pack(float x, float y) {
    __half2 h = __float22half2_rn(make_float2(x, y));
    return *(unsigned*)&h;
}

// ---------------- fused flash attention (HMMA, hi/lo fp16 split) -------------
#define PLANEW 2304   // 64 rows * 36 words
__global__ __launch_bounds__(128, 3) void attn_k(
    const unsigned* __restrict__ Q, const unsigned* __restrict__ K,
    const unsigned* __restrict__ V, const float* __restrict__ mask,
    float* __restrict__ out)
{
    extern __shared__ unsigned smw[];
    unsigned* qhi = smw;
    unsigned* qlo = smw + PLANEW;
    unsigned* khi = smw + 2 * PLANEW;
    unsigned* klo = smw + 3 * PLANEW;
    unsigned* vhi = smw + 4 * PLANEW;
    unsigned* vlo = smw + 5 * PLANEW;
    float* Ms = (float*)(smw + 6 * PLANEW);

    int bh = blockIdx.x, qt = blockIdx.y;
    int b = bh >> 4, h = bh & 15;
    int tid = threadIdx.x, w = tid >> 5, lane = tid & 31;
    int g = lane >> 2, t = lane & 3;

    const unsigned* Qg = Q + (bh * 1024 + qt * 64) * 64;
    for (int i = tid; i < 2048; i += 128) {
        int q = i >> 5, dp = i & 31;
        uint2 u = *(const uint2*)&Qg[q * 64 + 2 * dp];
        qhi[q * 36 + dp] = __byte_perm(u.x, u.y, 0x5410);
        qlo[q * 36 + dp] = __byte_perm(u.x, u.y, 0x7632);
    }
    __syncthreads();

    unsigned qh[4][4], ql[4][4];
    int qr = w * 16 + g;
#pragma unroll
    for (int c = 0; c < 4; c++) {
        int wp = c * 8 + t;
        qh[c][0] = qhi[qr * 36 + wp];
        qh[c][1] = qhi[(qr + 8) * 36 + wp];
        qh[c][2] = qhi[qr * 36 + wp + 4];
        qh[c][3] = qhi[(qr + 8) * 36 + wp + 4];
        ql[c][0] = qlo[qr * 36 + wp];
        ql[c][1] = qlo[(qr + 8) * 36 + wp];
        ql[c][2] = qlo[qr * 36 + wp + 4];
        ql[c][3] = qlo[(qr + 8) * 36 + wp + 4];
    }

    float m0r = -1e30f, m1r = -1e30f, l0r = 0.f, l1r = 0.f;
    float O[8][4];
#pragma unroll
    for (int n = 0; n < 8; n++)
#pragma unroll
        for (int e = 0; e < 4; e++) O[n][e] = 0.f;

    const float* maskb = mask + (b << 10);
    unsigned base0 = ((unsigned)bh << 20) | ((unsigned)(qt * 64 + qr) << 10);

    for (int kt = 0; kt < 16; kt++) {
        __syncthreads();
        const unsigned* Kg = K + (bh * 1024 + kt * 64) * 64;
        const unsigned* Vg = V + (bh * 1024 + kt * 64) * 64;
        for (int i = tid; i < 2048; i += 128) {
            int k = i >> 5, dp = i & 31;
            uint2 u = *(const uint2*)&Kg[k * 64 + 2 * dp];
            khi[k * 36 + dp] = __byte_perm(u.x, u.y, 0x5410);
            klo[k * 36 + dp] = __byte_perm(u.x, u.y, 0x7632);
            int d = i & 63, kp = i >> 6;
            unsigned v0 = Vg[(2 * kp) * 64 + d];
            unsigned v1 = Vg[(2 * kp + 1) * 64 + d];
            int col = kp ^ ((d >> 3) & 3);
            vhi[d * 36 + col] = __byte_perm(v0, v1, 0x5410);
            vlo[d * 36 + col] = __byte_perm(v0, v1, 0x7632);
        }
        if (tid < 64) Ms[tid] = maskb[kt * 64 + tid];
        __syncthreads();

        float S[8][4];
#pragma unroll
        for (int n = 0; n < 8; n++)
#pragma unroll
            for (int e = 0; e < 4; e++) S[n][e] = 0.f;

#pragma unroll
        for (int j = 0; j < 8; j++) {
            int krow = j * 8 + g;
#pragma unroll
            for (int c = 0; c < 4; c++) {
                int wp = c * 8 + t;
                unsigned bh0 = khi[krow * 36 + wp];
                unsigned bh1 = khi[krow * 36 + wp + 4];
                unsigned bl0 = klo[krow * 36 + wp];
                unsigned bl1 = klo[krow * 36 + wp + 4];
                mma16816(S[j][0], S[j][1], S[j][2], S[j][3],
                         qh[c][0], qh[c][1], qh[c][2], qh[c][3], bh0, bh1);
                mma16816(S[j][0], S[j][1], S[j][2], S[j][3],
                         qh[c][0], qh[c][1], qh[c][2], qh[c][3], bl0, bl1);
                mma16816(S[j][0], S[j][1], S[j][2], S[j][3],
                         ql[c][0], ql[c][1], ql[c][2], ql[c][3], bh0, bh1);
            }
        }

#pragma unroll
        for (int j = 0; j < 8; j++) {
            unsigned kc = (unsigned)(kt * 64 + j * 8 + 2 * t);
            float mv0 = Ms[j * 8 + 2 * t], mv1 = Ms[j * 8 + 2 * t + 1];
            S[j][0] = fmaf(S[j][0], 0.125f, noise_at(base0 + kc) + mv0);
            S[j][1] = fmaf(S[j][1], 0.125f, noise_at(base0 + kc + 1) + mv1);
            S[j][2] = fmaf(S[j][2], 0.125f, noise_at(base0 + (8u << 10) + kc) + mv0);
            S[j][3] = fmaf(S[j][3], 0.125f, noise_at(base0 + (8u << 10) + kc + 1) + mv1);
        }

        float tm0 = -1e30f, tm1 = -1e30f;
#pragma unroll
        for (int j = 0; j < 8; j++) {
            tm0 = fmaxf(tm0, fmaxf(S[j][0], S[j][1]));
            tm1 = fmaxf(tm1, fmaxf(S[j][2], S[j][3]));
        }
        tm0 = fmaxf(tm0, __shfl_xor_sync(0xffffffffu, tm0, 1));
        tm0 = fmaxf(tm0, __shfl_xor_sync(0xffffffffu, tm0, 2));
        tm1 = fmaxf(tm1, __shfl_xor_sync(0xffffffffu, tm1, 1));
        tm1 = fmaxf(tm1, __shfl_xor_sync(0xffffffffu, tm1, 2));
        float mn0 = fmaxf(m0r, tm0), mn1 = fmaxf(m1r, tm1);
        float cor0 = __expf(m0r - mn0), cor1 = __expf(m1r - mn1);
        m0r = mn0; m1r = mn1;
        float ps0 = 0.f, ps1 = 0.f;
#pragma unroll
        for (int j = 0; j < 8; j++) {
            S[j][0] = __expf(S[j][0] - mn0); S[j][1] = __expf(S[j][1] - mn0);
            S[j][2] = __expf(S[j][2] - mn1); S[j][3] = __expf(S[j][3] - mn1);
            ps0 += S[j][0] + S[j][1];
            ps1 += S[j][2] + S[j][3];
        }
        ps0 += __shfl_xor_sync(0xffffffffu, ps0, 1);
        ps0 += __shfl_xor_sync(0xffffffffu, ps0, 2);
        ps1 += __shfl_xor_sync(0xffffffffu, ps1, 1);
        ps1 += __shfl_xor_sync(0xffffffffu, ps1, 2);
        l0r = l0r * cor0 + ps0;
        l1r = l1r * cor1 + ps1;
#pragma unroll
        for (int n = 0; n < 8; n++) {
            O[n][0] *= cor0; O[n][1] *= cor0;
            O[n][2] *= cor1; O[n][3] *= cor1;
        }

        unsigned ph[4][4], pl[4][4];
#pragma unroll
        for (int c = 0; c < 4; c++) {
            float v0 = S[2 * c][0],     v1 = S[2 * c][1];
            float v2 = S[2 * c][2],     v3 = S[2 * c][3];
            float v4 = S[2 * c + 1][0], v5 = S[2 * c + 1][1];
            float v6 = S[2 * c + 1][2], v7 = S[2 * c + 1][3];
            ph[c][0] = h2pack(v0, v1);
            ph[c][1] = h2pack(v2, v3);
            ph[c][2] = h2pack(v4, v5);
            ph[c][3] = h2pack(v6, v7);
            __half2* hp;
            hp = (__half2*)&ph[c][0];
            pl[c][0] = h2pack(v0 - __half2float(hp->x), v1 - __half2float(hp->y));
            hp = (__half2*)&ph[c][1];
            pl[c][1] = h2pack(v2 - __half2float(hp->x), v3 - __half2float(hp->y));
            hp = (__half2*)&ph[c][2];
            pl[c][2] = h2pack(v4 - __half2float(hp->x), v5 - __half2float(hp->y));
            hp = (__half2*)&ph[c][3];
            pl[c][3] = h2pack(v6 - __half2float(hp->x), v7 - __half2float(hp->y));
        }

#pragma unroll
        for (int n = 0; n < 8; n++) {
            int vrow = n * 8 + g;
            int vs = n & 3;
#pragma unroll
            for (int c = 0; c < 4; c++) {
                int wp0 = (c * 8 + t) ^ vs;
                int wp1 = (c * 8 + 4 + t) ^ vs;
                unsigned bh0 = vhi[vrow * 36 + wp0];
                unsigned bh1 = vhi[vrow * 36 + wp1];
                unsigned bl0 = vlo[vrow * 36 + wp0];
                unsigned bl1 = vlo[vrow * 36 + wp1];
                mma16816(O[n][0], O[n][1], O[n][2], O[n][3],
                         ph[c][0], ph[c][1], ph[c][2], ph[c][3], bh0, bh1);
                mma16816(O[n][0], O[n][1], O[n][2], O[n][3],
                         ph[c][0], ph[c][1], ph[c][2], ph[c][3], bl0, bl1);
                mma16816(O[n][0], O[n][1], O[n][2], O[n][3],
                         pl[c][0], pl[c][1], pl[c][2], pl[c][3], bh0, bh1);
            }
        }
    }

    float inv0 = 1.0f / l0r, inv1 = 1.0f / l1r;
    int q0 = qt * 64 + qr;
    float* o0 = out + ((size_t)((b << 10) + q0)) * 1024 + (h << 6);
    float* o1 = out + ((size_t)((b << 10) + q0 + 8)) * 1024 + (h << 6);
#pragma unroll
    for (int n = 0; n < 8; n++) {
        int dh = n * 8 + 2 * t;
        *(float2*)(o0 + dh) = make_float2(O[n][0] * inv0, O[n][1] * inv0);
        *(float2*)(o1 + dh) = make_float2(O[n][2] * inv1, O[n][3] * inv1);
    }
}

// ---------------- launch -----------------------------------------------------
extern "C" void kernel_launch(void* const* d_in, const int* in_sizes, int n_in,
                              void* d_out, int out_size) {
    const float* hidden = (const float*)d_in[0];
    const float* mask   = (const float*)d_in[1];
    const float* Wq     = (const float*)d_in[2];
    const float* Wk     = (const float*)d_in[3];
    const float* Wv     = (const float*)d_in[4];
    float* out = (float*)d_out;

    int *hq8, *r8, *wq8, *wk8, *wv8;
    unsigned *Qp, *Kp, *Vp;
    cudaGetSymbolAddress((void**)&hq8, g_hq8);
    cudaGetSymbolAddress((void**)&r8,  g_r8);
    cudaGetSymbolAddress((void**)&wq8, g_wq8);
    cudaGetSymbolAddress((void**)&wk8, g_wk8);
    cudaGetSymbolAddress((void**)&wv8, g_wv8);
    cudaGetSymbolAddress((void**)&Qp,  g_Qh);
    cudaGetSymbolAddress((void**)&Kp,  g_Kh);
    cudaGetSymbolAddress((void**)&Vp,  g_Vh);

    init_k<<<1, 32>>>();
    absmax_all_k<<<dim3(128, 1, 4), 256>>>((const float4*)hidden, (const float4*)Wq,
                                           (const float4*)Wk, (const float4*)Wv);
    pack_all_k<<<dim3(256, 1, 4), 256>>>((const float4*)hidden, (const float4*)Wq,
                                         (const float4*)Wk, (const float4*)Wv,
                                         hq8, r8, wq8, wk8, wv8);

    gemm_imma<0><<<dim3(8, 32, 2), 256>>>(hq8, r8, wq8, wk8, wv8, Qp, Kp, Vp);
    gemm_imma<1><<<dim3(8, 32, 1), 256>>>(hq8, r8, wq8, wk8, wv8, Qp, Kp, Vp);

    int smem_bytes = 6 * PLANEW * 4 + 64 * 4;
    cudaFuncSetAttribute(attn_k, cudaFuncAttributeMaxDynamicSharedMemorySize, smem_bytes);
    attn_k<<<dim3(64, 16), 128, smem_bytes>>>(Qp, Kp, Vp, mask, out);
}

// round 12
// speedup vs baseline: 1.3047x; 1.0859x over previous
#include <cuda_runtime.h>
#include <cuda_fp16.h>
#include <cstdint>

// ---------------- scratch (__device__ globals; no allocs allowed) ------------
__device__ int      g_hq8[1048576];   // hidden quantized int8, packed 4/int32
__device__ int      g_r8 [1048576];   // residual quantized int8, packed
__device__ int      g_wq8[262144];
__device__ int      g_wk8[262144];
__device__ int      g_wv8[262144];
__device__ unsigned g_Qh[4194304];    // [B*H, S, 64] packed {fp16 hi, fp16 lo}
__device__ unsigned g_Kh[4194304];
__device__ unsigned g_Vh[4194304];
__device__ unsigned int g_absmax[4];  // 0:hidden 1:Wq 2:Wk 3:Wv

// ---------------- absmax / packing ------------------------------------------
__global__ void init_k() {
    if (threadIdx.x < 4) g_absmax[threadIdx.x] = 0u;
}

__global__ void absmax_all_k(const float4* __restrict__ hid, const float4* __restrict__ wq,
                             const float4* __restrict__ wk, const float4* __restrict__ wv) {
    int z = blockIdx.z;
    const float4* x = (z == 0) ? hid : (z == 1) ? wq : (z == 2) ? wk : wv;
    int n4 = (z == 0) ? 1048576 : 262144;
    float m = 0.f;
    for (int i = blockIdx.x * blockDim.x + threadIdx.x; i < n4; i += gridDim.x * blockDim.x) {
        float4 v = x[i];
        m = fmaxf(m, fmaxf(fmaxf(fabsf(v.x), fabsf(v.y)), fmaxf(fabsf(v.z), fabsf(v.w))));
    }
#pragma unroll
    for (int o = 16; o > 0; o >>= 1) m = fmaxf(m, __shfl_xor_sync(0xffffffffu, m, o));
    if ((threadIdx.x & 31) == 0) atomicMax(&g_absmax[z], __float_as_uint(m));
}

__device__ __forceinline__ int pack4i(float a, float b, float c, float d) {
    int ia = (int)a, ib = (int)b, ic = (int)c, id = (int)d;
    return (ia & 0xFF) | ((ib & 0xFF) << 8) | ((ic & 0xFF) << 16) | ((id & 0xFF) << 24);
}

__global__ void pack_all_k(const float4* __restrict__ hid, const float4* __restrict__ wq,
                           const float4* __restrict__ wk, const float4* __restrict__ wv,
                           int* __restrict__ q8, int* __restrict__ r8,
                           int* __restrict__ yq, int* __restrict__ yk, int* __restrict__ yv) {
    int z = blockIdx.z;
    if (z == 0) {
        float s  = fmaxf(__uint_as_float(g_absmax[0]), 1e-8f) / 127.0f;
        float s2 = s / 254.0f;
        for (int i = blockIdx.x * blockDim.x + threadIdx.x; i < 1048576;
             i += gridDim.x * blockDim.x) {
            float4 v = hid[i];
            float qa = fminf(fmaxf(rintf(v.x / s), -127.f), 127.f);
            float qb = fminf(fmaxf(rintf(v.y / s), -127.f), 127.f);
            float qc = fminf(fmaxf(rintf(v.z / s), -127.f), 127.f);
            float qd = fminf(fmaxf(rintf(v.w / s), -127.f), 127.f);
            q8[i] = pack4i(qa, qb, qc, qd);
            float ra = fminf(fmaxf(rintf((v.x - qa * s) / s2), -127.f), 127.f);
            float rb = fminf(fmaxf(rintf((v.y - qb * s) / s2), -127.f), 127.f);
            float rc = fminf(fmaxf(rintf((v.z - qc * s) / s2), -127.f), 127.f);
            float rd = fminf(fmaxf(rintf((v.w - qd * s) / s2), -127.f), 127.f);
            r8[i] = pack4i(ra, rb, rc, rd);
        }
    } else {
        const float4* x = (z == 1) ? wq : (z == 2) ? wk : wv;
        int* y = (z == 1) ? yq : (z == 2) ? yk : yv;
        float s = fmaxf(__uint_as_float(g_absmax[z]), 1e-8f) / 7.0f;
        for (int i = blockIdx.x * blockDim.x + threadIdx.x; i < 262144;
             i += gridDim.x * blockDim.x) {
            float4 v = x[i];
            float a = fminf(fmaxf(rintf(v.x / s), -7.f), 7.f);
            float b = fminf(fmaxf(rintf(v.y / s), -7.f), 7.f);
            float c = fminf(fmaxf(rintf(v.z / s), -7.f), 7.f);
            float d = fminf(fmaxf(rintf(v.w / s), -7.f), 7.f);
            y[i] = pack4i(a, b, c, d);
        }
    }
}

// fp32 -> packed {half hi, half lo}; x == hi + lo to ~2^-22 relative
__device__ __forceinline__ unsigned pack_f2h(float x) {
    __half h = __float2half_rn(x);
    __half l = __float2half_rn(x - __half2float(h));
    return (unsigned)__half_as_ushort(h) | ((unsigned)__half_as_ushort(l) << 16);
}

// ---------------- IMMA int8 tensor-core GEMM --------------------------------
__device__ __forceinline__ void imma16832(int& c0, int& c1, int& c2, int& c3,
                                          int a0, int a1, int a2, int a3,
                                          int b0, int b1) {
    asm volatile(
        "mma.sync.aligned.m16n8k32.row.col.s32.s8.s8.s32 "
        "{%0,%1,%2,%3},{%4,%5,%6,%7},{%8,%9},{%0,%1,%2,%3};"
        : "+r"(c0), "+r"(c1), "+r"(c2), "+r"(c3)
        : "r"(a0), "r"(a1), "r"(a2), "r"(a3), "r"(b0), "r"(b1));
}

__device__ __forceinline__ unsigned out_idx(int m, int n) {
    int bb = m >> 10, s = m & 1023, h = n >> 6, dh = n & 63;
    return (unsigned)(((bb * 16 + h) << 16) + (s << 6) + dh);
}

__device__ __forceinline__ uint32_t smem_u32(const void* p) {
    uint32_t a;
    asm("{ .reg .u64 t; cvta.to.shared.u64 t, %1; cvt.u32.u64 %0, t; }" : "=r"(a) : "l"(p));
    return a;
}

__device__ __forceinline__ void cp16(uint32_t d, const void* s) {
    asm volatile("cp.async.cg.shared.global [%0], [%1], 16;" :: "r"(d), "l"(s));
}

// C[m,n] = sum_d A[m,d]*W[n,d]; 128x128 tile, K=1024 int8 (256 int32/row).
// 256 threads = 8 warps (2m x 4n), warp tile 64x32. cp.async double-buffered.
// ISV=0: Q/K (z selects weight; acc1 only -> 2 blocks/SM).
// ISV=1: V = (hq8, r8) @ Wv combined.
template <int ISV>
__global__ __launch_bounds__(256, ISV ? 1 : 2) void gemm_imma(
    const int* __restrict__ A8, const int* __restrict__ R8,
    const int* __restrict__ wq8, const int* __restrict__ wk8, const int* __restrict__ wv8,
    unsigned* __restrict__ Qo, unsigned* __restrict__ Ko, unsigned* __restrict__ Vo)
{
    extern __shared__ int gsm[];   // [2 bufs x 2560] per array: A | B | (R)
    int* AsB = gsm;
    int* BsB = gsm + 5120;
    int* RsB = gsm + 10240;

    int z = ISV ? 2 : blockIdx.z;
    const int* W = (z == 0) ? wq8 : (z == 1) ? wk8 : wv8;

    int tid = threadIdx.x;
    int m0 = blockIdx.y * 128, n0 = blockIdx.x * 128;
    int w = tid >> 5, lane = tid & 31, g = lane >> 2, t = lane & 3;
    int wm = (w >> 2) * 64, wn = (w & 3) * 32;

    int acc1[4][4][4];
    int acc2[ISV ? 4 : 1][ISV ? 4 : 1][4];
#pragma unroll
    for (int mi = 0; mi < 4; mi++)
#pragma unroll
        for (int ni = 0; ni < 4; ni++)
#pragma unroll
            for (int e = 0; e < 4; e++) acc1[mi][ni][e] = 0;
    if (ISV) {
#pragma unroll
        for (int mi = 0; mi < 4; mi++)
#pragma unroll
            for (int ni = 0; ni < 4; ni++)
#pragma unroll
                for (int e = 0; e < 4; e++) acc2[mi][ni][e] = 0;
    }

    int srow = tid >> 1, shalf = (tid & 1) * 8;
    const int* Ag = A8 + (m0 + srow) * 256 + shalf;
    const int* Rg = R8 + (m0 + srow) * 256 + shalf;
    const int* Wg = W  + (n0 + srow) * 256 + shalf;
    int sboff = (srow * 20 + shalf) * 4;   // byte offset inside one buffer

    uint32_t sA = smem_u32(AsB), sB = smem_u32(BsB), sR = smem_u32(RsB);

    // prologue: stage slab 0 into buffer 0
    {
        cp16(sA + sboff, Ag);      cp16(sA + sboff + 16, Ag + 4);
        cp16(sB + sboff, Wg);      cp16(sB + sboff + 16, Wg + 4);
        if (ISV) { cp16(sR + sboff, Rg); cp16(sR + sboff + 16, Rg + 4); }
        asm volatile("cp.async.commit_group;");
    }

    for (int ks = 0; ks < 16; ks++) {
        int cur = ks & 1, nxt = cur ^ 1;
        if (ks < 15) {
            uint32_t boff = (uint32_t)nxt * 10240u + (uint32_t)sboff;
            const int* a = Ag + (ks + 1) * 16;
            const int* b = Wg + (ks + 1) * 16;
            cp16(sA + boff, a); cp16(sA + boff + 16, a + 4);
            cp16(sB + boff, b); cp16(sB + boff + 16, b + 4);
            if (ISV) {
                const int* r = Rg + (ks + 1) * 16;
                cp16(sR + boff, r); cp16(sR + boff + 16, r + 4);
            }
            asm volatile("cp.async.commit_group;");
            asm volatile("cp.async.wait_group 1;");
        } else {
            asm volatile("cp.async.wait_group 0;");
        }
        __syncthreads();

        const int* Asw = AsB + cur * 2560;
        const int* Bsw = BsB + cur * 2560;
        const int* Rsw = RsB + cur * 2560;

#pragma unroll
        for (int kk = 0; kk < 2; kk++) {
            int bb0[4], bb1[4];
#pragma unroll
            for (int ni = 0; ni < 4; ni++) {
                int brow = (wn + ni * 8 + g) * 20 + kk * 8;
                bb0[ni] = Bsw[brow + t];
                bb1[ni] = Bsw[brow + 4 + t];
            }
#pragma unroll
            for (int mi = 0; mi < 4; mi++) {
                int ar0 = (wm + mi * 16 + g) * 20 + kk * 8;
                int ar1 = (wm + mi * 16 + 8 + g) * 20 + kk * 8;
                int a0 = Asw[ar0 + t], a1 = Asw[ar1 + t];
                int a2 = Asw[ar0 + 4 + t], a3 = Asw[ar1 + 4 + t];
#pragma unroll
                for (int ni = 0; ni < 4; ni++)
                    imma16832(acc1[mi][ni][0], acc1[mi][ni][1], acc1[mi][ni][2], acc1[mi][ni][3],
                              a0, a1, a2, a3, bb0[ni], bb1[ni]);
                if (ISV) {
                    int r0 = Rsw[ar0 + t], r1 = Rsw[ar1 + t];
                    int r2 = Rsw[ar0 + 4 + t], r3 = Rsw[ar1 + 4 + t];
#pragma unroll
                    for (int ni = 0; ni < 4; ni++)
                        imma16832(acc2[mi][ni][0], acc2[mi][ni][1], acc2[mi][ni][2], acc2[mi][ni][3],
                                  r0, r1, r2, r3, bb0[ni], bb1[ni]);
                }
            }
        }
        __syncthreads();
    }

    float sa = fmaxf(__uint_as_float(g_absmax[0]), 1e-8f) / 127.0f;
    float sw = fmaxf(__uint_as_float(g_absmax[z + 1]), 1e-8f) / 7.0f;
    float k1 = sa * sw;
    float k2 = (sa / 254.0f) * sw;
    unsigned* O = (z == 0) ? Qo : (z == 1) ? Ko : Vo;

#pragma unroll
    for (int mi = 0; mi < 4; mi++) {
        int r0 = m0 + wm + mi * 16 + g;
        int r1 = r0 + 8;
#pragma unroll
        for (int ni = 0; ni < 4; ni++) {
            int c0 = n0 + wn + ni * 8 + 2 * t;
            if (!ISV) {
                O[out_idx(r0, c0)]     = pack_f2h((float)acc1[mi][ni][0] * k1);
                O[out_idx(r0, c0 + 1)] = pack_f2h((float)acc1[mi][ni][1] * k1);
                O[out_idx(r1, c0)]     = pack_f2h((float)acc1[mi][ni][2] * k1);
                O[out_idx(r1, c0 + 1)] = pack_f2h((float)acc1[mi][ni][3] * k1);
            } else {
                O[out_idx(r0, c0)]     = pack_f2h(fmaf((float)acc2[mi][ni][0], k2, (float)acc1[mi][ni][0] * k1));
                O[out_idx(r0, c0 + 1)] = pack_f2h(fmaf((float)acc2[mi][ni][1], k2, (float)acc1[mi][ni][1] * k1));
                O[out_idx(r1, c0)]     = pack_f2h(fmaf((float)acc2[mi][ni][2], k2, (float)acc1[mi][ni][2] * k1));
                O[out_idx(r1, c0 + 1)] = pack_f2h(fmaf((float)acc2[mi][ni][3], k2, (float)acc1[mi][ni][3] * k1));
            }
        }
    }
}

// ---------------- JAX threefry2x32 noise (partitionable, key=(0,42)) --------
__device__ __forceinline__ uint32_t rotl32(uint32_t x, int r) {
    return (x << r) | (x >> (32 - r));
}

__device__ __forceinline__ void threefry2x32(uint32_t c0, uint32_t c1,
                                             uint32_t& o0, uint32_t& o1) {
    const uint32_t k0 = 0u, k1 = 42u, k2 = 0u ^ 42u ^ 0x1BD11BDAu;
    uint32_t x0 = c0 + k0, x1 = c1 + k1;
#define TF_R(r) { x0 += x1; x1 = rotl32(x1, r); x1 ^= x0; }
    TF_R(13) TF_R(15) TF_R(26) TF_R(6)
    x0 += k1; x1 += k2 + 1u;
    TF_R(17) TF_R(29) TF_R(16) TF_R(24)
    x0 += k2; x1 += k0 + 2u;
    TF_R(13) TF_R(15) TF_R(26) TF_R(6)
    x0 += k0; x1 += k1 + 3u;
    TF_R(17) TF_R(29) TF_R(16) TF_R(24)
    x0 += k1; x1 += k2 + 4u;
    TF_R(13) TF_R(15) TF_R(26) TF_R(6)
    x0 += k2; x1 += k0 + 5u;
#undef TF_R
    o0 = x0; o1 = x1;
}

__device__ __forceinline__ float noise_at(unsigned int i) {
    uint32_t o0, o1;
    threefry2x32(0u, i, o0, o1);
    uint32_t bits = o0 ^ o1;
    float f = __uint_as_float((bits >> 9) | 0x3f800000u) - 1.0f;
    const float lo = -0.99999994f;
    float u = fmaxf(lo, fmaf(f, 2.0f, lo));
    float t = fmaf(-u, u, 1.0f);
    float w = -__logf(t);
    float p;
    if (w < 5.0f) {
        w = w - 2.5f;
        p = 2.81022636e-08f;
        p = fmaf(p, w, 3.43273939e-07f);
        p = fmaf(p, w, -3.5233877e-06f);
        p = fmaf(p, w, -4.39150654e-06f);
        p = fmaf(p, w, 0.00021858087f);
        p = fmaf(p, w, -0.00125372503f);
        p = fmaf(p, w, -0.00417768164f);
        p = fmaf(p, w, 0.246640727f);
        p = fmaf(p, w, 1.50140941f);
    } else {
        w = sqrtf(w) - 3.0f;
        p = -0.000200214257f;
        p = fmaf(p, w, 0.000100950558f);
        p = fmaf(p, w, 0.00134934322f);
        p = fmaf(p, w, -0.00367342844f);
        p = fmaf(p, w, 0.00573950773f);
        p = fmaf(p, w, -0.0076224613f);
        p = fmaf(p, w, 0.00943887047f);
        p = fmaf(p, w, 1.00167406f);
        p = fmaf(p, w, 2.83297682f);
    }
    return 1.41421356f * (p * u) * 0.05f;
}

// ---------------- HMMA helpers ----------------------------------------------
__device__ __forceinline__ void mma16816(float& c0, float& c1, float& c2, float& c3,
                                         unsigned a0, unsigned a1, unsigned a2, unsigned a3,
                                         unsigned b0, unsigned b1) {
    asm volatile(
        "mma.sync.aligned.m16n8k16.row.col.f32.f16.f16.f32 "
        "{%0,%1,%2,%3},{%4,%5,%6,%7},{%8,%9},{%0,%1,%2,%3};"
        : "+f"(c0), "+f"(c1), "+f"(c2), "+f"(c3)
        : "r"(a0), "r"(a1), "r"(a2), "r"(a3), "r"(b0), "r"(b1));
}

__device__ __forceinline__ unsigned h2pack(float x, float y) {
    __half2 h = __float22half2_rn(make_float2(x, y));
    return *(unsigned*)&h;
}

// ---------------- fused flash attention (HMMA, 2-term hi/lo) -----------------
// Q: fp16 hi only (residual dropped). K/V: hi+lo planes (full split).
// P: fp16 hi only (residual dropped).
// Planes as 32-bit words, row stride 36; V^T XOR-swizzled.
#define PLANEW 2304   // 64 rows * 36 words
__global__ __launch_bounds__(128, 3) void attn_k(
    const unsigned* __restrict__ Q, const unsigned* __restrict__ K,
    const unsigned* __restrict__ V, const float* __restrict__ mask,
    float* __restrict__ out)
{
    extern __shared__ unsigned smw[];
    unsigned* qhi = smw;
    unsigned* khi = smw + PLANEW;
    unsigned* klo = smw + 2 * PLANEW;
    unsigned* vhi = smw + 3 * PLANEW;
    unsigned* vlo = smw + 4 * PLANEW;
    float* Ms = (float*)(smw + 5 * PLANEW);

    int bh = blockIdx.x, qt = blockIdx.y;
    int b = bh >> 4, h = bh & 15;
    int tid = threadIdx.x, w = tid >> 5, lane = tid & 31;
    int g = lane >> 2, t = lane & 3;

    const unsigned* Qg = Q + (bh * 1024 + qt * 64) * 64;
    for (int i = tid; i < 2048; i += 128) {
        int q = i >> 5, dp = i & 31;
        uint2 u = *(const uint2*)&Qg[q * 64 + 2 * dp];
        qhi[q * 36 + dp] = __byte_perm(u.x, u.y, 0x5410);
    }
    __syncthreads();

    unsigned qh[4][4];
    int qr = w * 16 + g;
#pragma unroll
    for (int c = 0; c < 4; c++) {
        int wp = c * 8 + t;
        qh[c][0] = qhi[qr * 36 + wp];
        qh[c][1] = qhi[(qr + 8) * 36 + wp];
        qh[c][2] = qhi[qr * 36 + wp + 4];
        qh[c][3] = qhi[(qr + 8) * 36 + wp + 4];
    }

    float m0r = -1e30f, m1r = -1e30f, l0r = 0.f, l1r = 0.f;
    float O[8][4];
#pragma unroll
    for (int n = 0; n < 8; n++)
#pragma unroll
        for (int e = 0; e < 4; e++) O[n][e] = 0.f;

    const float* maskb = mask + (b << 10);
    unsigned base0 = ((unsigned)bh << 20) | ((unsigned)(qt * 64 + qr) << 10);

    for (int kt = 0; kt < 16; kt++) {
        __syncthreads();
        const unsigned* Kg = K + (bh * 1024 + kt * 64) * 64;
        const unsigned* Vg = V + (bh * 1024 + kt * 64) * 64;
        for (int i = tid; i < 2048; i += 128) {
            int k = i >> 5, dp = i & 31;
            uint2 u = *(const uint2*)&Kg[k * 64 + 2 * dp];
            khi[k * 36 + dp] = __byte_perm(u.x, u.y, 0x5410);
            klo[k * 36 + dp] = __byte_perm(u.x, u.y, 0x7632);
            int d = i & 63, kp = i >> 6;
            unsigned v0 = Vg[(2 * kp) * 64 + d];
            unsigned v1 = Vg[(2 * kp + 1) * 64 + d];
            int col = kp ^ ((d >> 3) & 3);
            vhi[d * 36 + col] = __byte_perm(v0, v1, 0x5410);
            vlo[d * 36 + col] = __byte_perm(v0, v1, 0x7632);
        }
        if (tid < 64) Ms[tid] = maskb[kt * 64 + tid];
        __syncthreads();

        // ---- S = Q K^T: 2-term (qh*khi + qh*klo)
        float S[8][4];
#pragma unroll
        for (int n = 0; n < 8; n++)
#pragma unroll
            for (int e = 0; e < 4; e++) S[n][e] = 0.f;

#pragma unroll
        for (int j = 0; j < 8; j++) {
            int krow = j * 8 + g;
#pragma unroll
            for (int c = 0; c < 4; c++) {
                int wp = c * 8 + t;
                unsigned bh0 = khi[krow * 36 + wp];
                unsigned bh1 = khi[krow * 36 + wp + 4];
                unsigned bl0 = klo[krow * 36 + wp];
                unsigned bl1 = klo[krow * 36 + wp + 4];
                mma16816(S[j][0], S[j][1], S[j][2], S[j][3],
                         qh[c][0], qh[c][1], qh[c][2], qh[c][3], bh0, bh1);
                mma16816(S[j][0], S[j][1], S[j][2], S[j][3],
                         qh[c][0], qh[c][1], qh[c][2], qh[c][3], bl0, bl1);
            }
        }

        // ---- scale + noise + mask
#pragma unroll
        for (int j = 0; j < 8; j++) {
            unsigned kc = (unsigned)(kt * 64 + j * 8 + 2 * t);
            float mv0 = Ms[j * 8 + 2 * t], mv1 = Ms[j * 8 + 2 * t + 1];
            S[j][0] = fmaf(S[j][0], 0.125f, noise_at(base0 + kc) + mv0);
            S[j][1] = fmaf(S[j][1], 0.125f, noise_at(base0 + kc + 1) + mv1);
            S[j][2] = fmaf(S[j][2], 0.125f, noise_at(base0 + (8u << 10) + kc) + mv0);
            S[j][3] = fmaf(S[j][3], 0.125f, noise_at(base0 + (8u << 10) + kc + 1) + mv1);
        }

        // ---- online softmax
        float tm0 = -1e30f, tm1 = -1e30f;
#pragma unroll
        for (int j = 0; j < 8; j++) {
            tm0 = fmaxf(tm0, fmaxf(S[j][0], S[j][1]));
            tm1 = fmaxf(tm1, fmaxf(S[j][2], S[j][3]));
        }
        tm0 = fmaxf(tm0, __shfl_xor_sync(0xffffffffu, tm0, 1));
        tm0 = fmaxf(tm0, __shfl_xor_sync(0xffffffffu, tm0, 2));
        tm1 = fmaxf(tm1, __shfl_xor_sync(0xffffffffu, tm1, 1));
        tm1 = fmaxf(tm1, __shfl_xor_sync(0xffffffffu, tm1, 2));
        float mn0 = fmaxf(m0r, tm0), mn1 = fmaxf(m1r, tm1);
        float cor0 = __expf(m0r - mn0), cor1 = __expf(m1r - mn1);
        m0r = mn0; m1r = mn1;
        float ps0 = 0.f, ps1 = 0.f;
#pragma unroll
        for (int j = 0; j < 8; j++) {
            S[j][0] = __expf(S[j][0] - mn0); S[j][1] = __expf(S[j][1] - mn0);
            S[j][2] = __expf(S[j][2] - mn1); S[j][3] = __expf(S[j][3] - mn1);
            ps0 += S[j][0] + S[j][1];
            ps1 += S[j][2] + S[j][3];
        }
        ps0 += __shfl_xor_sync(0xffffffffu, ps0, 1);
        ps0 += __shfl_xor_sync(0xffffffffu, ps0, 2);
        ps1 += __shfl_xor_sync(0xffffffffu, ps1, 1);
        ps1 += __shfl_xor_sync(0xffffffffu, ps1, 2);
        l0r = l0r * cor0 + ps0;
        l1r = l1r * cor1 + ps1;
#pragma unroll
        for (int n = 0; n < 8; n++) {
            O[n][0] *= cor0; O[n][1] *= cor0;
            O[n][2] *= cor1; O[n][3] *= cor1;
        }

        // ---- P -> fp16 A-frags (hi only)
        unsigned ph[4][4];
#pragma unroll
        for (int c = 0; c < 4; c++) {
            ph[c][0] = h2pack(S[2 * c][0],     S[2 * c][1]);
            ph[c][1] = h2pack(S[2 * c][2],     S[2 * c][3]);
            ph[c][2] = h2pack(S[2 * c + 1][0], S[2 * c + 1][1]);
            ph[c][3] = h2pack(S[2 * c + 1][2], S[2 * c + 1][3]);
        }

        // ---- O += P V: 2-term (ph*vhi + ph*vlo)
#pragma unroll
        for (int n = 0; n < 8; n++) {
            int vrow = n * 8 + g;
            int vs = n & 3;
#pragma unroll
            for (int c = 0; c < 4; c++) {
                int wp0 = (c * 8 + t) ^ vs;
                int wp1 = (c * 8 + 4 + t) ^ vs;
                unsigned bh0 = vhi[vrow * 36 + wp0];
                unsigned bh1 = vhi[vrow * 36 + wp1];
                unsigned bl0 = vlo[vrow * 36 + wp0];
                unsigned bl1 = vlo[vrow * 36 + wp1];
                mma16816(O[n][0], O[n][1], O[n][2], O[n][3],
                         ph[c][0], ph[c][1], ph[c][2], ph[c][3], bh0, bh1);
                mma16816(O[n][0], O[n][1], O[n][2], O[n][3],
                         ph[c][0], ph[c][1], ph[c][2], ph[c][3], bl0, bl1);
            }
        }
    }

    float inv0 = 1.0f / l0r, inv1 = 1.0f / l1r;
    int q0 = qt * 64 + qr;
    float* o0 = out + ((size_t)((b << 10) + q0)) * 1024 + (h << 6);
    float* o1 = out + ((size_t)((b << 10) + q0 + 8)) * 1024 + (h << 6);
#pragma unroll
    for (int n = 0; n < 8; n++) {
        int dh = n * 8 + 2 * t;
        *(float2*)(o0 + dh) = make_float2(O[n][0] * inv0, O[n][1] * inv0);
        *(float2*)(o1 + dh) = make_float2(O[n][2] * inv1, O[n][3] * inv1);
    }
}

// ---------------- launch -----------------------------------------------------
extern "C" void kernel_launch(void* const* d_in, const int* in_sizes, int n_in,
                              void* d_out, int out_size) {
    const float* hidden = (const float*)d_in[0];
    const float* mask   = (const float*)d_in[1];
    const float* Wq     = (const float*)d_in[2];
    const float* Wk     = (const float*)d_in[3];
    const float* Wv     = (const float*)d_in[4];
    float* out = (float*)d_out;

    int *hq8, *r8, *wq8, *wk8, *wv8;
    unsigned *Qp, *Kp, *Vp;
    cudaGetSymbolAddress((void**)&hq8, g_hq8);
    cudaGetSymbolAddress((void**)&r8,  g_r8);
    cudaGetSymbolAddress((void**)&wq8, g_wq8);
    cudaGetSymbolAddress((void**)&wk8, g_wk8);
    cudaGetSymbolAddress((void**)&wv8, g_wv8);
    cudaGetSymbolAddress((void**)&Qp,  g_Qh);
    cudaGetSymbolAddress((void**)&Kp,  g_Kh);
    cudaGetSymbolAddress((void**)&Vp,  g_Vh);

    init_k<<<1, 32>>>();
    absmax_all_k<<<dim3(128, 1, 4), 256>>>((const float4*)hidden, (const float4*)Wq,
                                           (const float4*)Wk, (const float4*)Wv);
    pack_all_k<<<dim3(256, 1, 4), 256>>>((const float4*)hidden, (const float4*)Wq,
                                         (const float4*)Wk, (const float4*)Wv,
                                         hq8, r8, wq8, wk8, wv8);

    cudaFuncSetAttribute(gemm_imma<0>, cudaFuncAttributeMaxDynamicSharedMemorySize, 40960);
    cudaFuncSetAttribute(gemm_imma<1>, cudaFuncAttributeMaxDynamicSharedMemorySize, 61440);
    gemm_imma<0><<<dim3(8, 32, 2), 256, 40960>>>(hq8, r8, wq8, wk8, wv8, Qp, Kp, Vp);
    gemm_imma<1><<<dim3(8, 32, 1), 256, 61440>>>(hq8, r8, wq8, wk8, wv8, Qp, Kp, Vp);

    int smem_bytes = 5 * PLANEW * 4 + 64 * 4;
    cudaFuncSetAttribute(attn_k, cudaFuncAttributeMaxDynamicSharedMemorySize, smem_bytes);
    attn_k<<<dim3(64, 16), 128, smem_bytes>>>(Qp, Kp, Vp, mask, out);
}

// round 13
// speedup vs baseline: 1.4378x; 1.1021x over previous
#include <cuda_runtime.h>
#include <cuda_fp16.h>
#include <cstdint>

// ---------------- scratch (__device__ globals; no allocs allowed) ------------
__device__ int            g_hq8[1048576];   // hidden quantized int8, packed 4/int32
__device__ int            g_r8 [1048576];   // residual quantized int8, packed
__device__ int            g_wq8[262144];
__device__ int            g_wk8[262144];
__device__ int            g_wv8[262144];
__device__ unsigned short g_Q16[4194304];   // [B*H, S, 64] fp16
__device__ unsigned short g_K16[4194304];
__device__ unsigned short g_V16[4194304];
__device__ unsigned int   g_absmax[4];      // 0:hidden 1:Wq 2:Wk 3:Wv

// ---------------- absmax / packing ------------------------------------------
__global__ void init_k() {
    if (threadIdx.x < 4) g_absmax[threadIdx.x] = 0u;
}

__global__ void absmax_all_k(const float4* __restrict__ hid, const float4* __restrict__ wq,
                             const float4* __restrict__ wk, const float4* __restrict__ wv) {
    int z = blockIdx.z;
    const float4* x = (z == 0) ? hid : (z == 1) ? wq : (z == 2) ? wk : wv;
    int n4 = (z == 0) ? 1048576 : 262144;
    float m = 0.f;
    for (int i = blockIdx.x * blockDim.x + threadIdx.x; i < n4; i += gridDim.x * blockDim.x) {
        float4 v = x[i];
        m = fmaxf(m, fmaxf(fmaxf(fabsf(v.x), fabsf(v.y)), fmaxf(fabsf(v.z), fabsf(v.w))));
    }
#pragma unroll
    for (int o = 16; o > 0; o >>= 1) m = fmaxf(m, __shfl_xor_sync(0xffffffffu, m, o));
    if ((threadIdx.x & 31) == 0) atomicMax(&g_absmax[z], __float_as_uint(m));
}

__device__ __forceinline__ int pack4i(float a, float b, float c, float d) {
    int ia = (int)a, ib = (int)b, ic = (int)c, id = (int)d;
    return (ia & 0xFF) | ((ib & 0xFF) << 8) | ((ic & 0xFF) << 16) | ((id & 0xFF) << 24);
}

__global__ void pack_all_k(const float4* __restrict__ hid, const float4* __restrict__ wq,
                           const float4* __restrict__ wk, const float4* __restrict__ wv,
                           int* __restrict__ q8, int* __restrict__ r8,
                           int* __restrict__ yq, int* __restrict__ yk, int* __restrict__ yv) {
    int z = blockIdx.z;
    if (z == 0) {
        float s  = fmaxf(__uint_as_float(g_absmax[0]), 1e-8f) / 127.0f;
        float s2 = s / 254.0f;
        for (int i = blockIdx.x * blockDim.x + threadIdx.x; i < 1048576;
             i += gridDim.x * blockDim.x) {
            float4 v = hid[i];
            float qa = fminf(fmaxf(rintf(v.x / s), -127.f), 127.f);
            float qb = fminf(fmaxf(rintf(v.y / s), -127.f), 127.f);
            float qc = fminf(fmaxf(rintf(v.z / s), -127.f), 127.f);
            float qd = fminf(fmaxf(rintf(v.w / s), -127.f), 127.f);
            q8[i] = pack4i(qa, qb, qc, qd);
            float ra = fminf(fmaxf(rintf((v.x - qa * s) / s2), -127.f), 127.f);
            float rb = fminf(fmaxf(rintf((v.y - qb * s) / s2), -127.f), 127.f);
            float rc = fminf(fmaxf(rintf((v.z - qc * s) / s2), -127.f), 127.f);
            float rd = fminf(fmaxf(rintf((v.w - qd * s) / s2), -127.f), 127.f);
            r8[i] = pack4i(ra, rb, rc, rd);
        }
    } else {
        const float4* x = (z == 1) ? wq : (z == 2) ? wk : wv;
        int* y = (z == 1) ? yq : (z == 2) ? yk : yv;
        float s = fmaxf(__uint_as_float(g_absmax[z]), 1e-8f) / 7.0f;
        for (int i = blockIdx.x * blockDim.x + threadIdx.x; i < 262144;
             i += gridDim.x * blockDim.x) {
            float4 v = x[i];
            float a = fminf(fmaxf(rintf(v.x / s), -7.f), 7.f);
            float b = fminf(fmaxf(rintf(v.y / s), -7.f), 7.f);
            float c = fminf(fmaxf(rintf(v.z / s), -7.f), 7.f);
            float d = fminf(fmaxf(rintf(v.w / s), -7.f), 7.f);
            y[i] = pack4i(a, b, c, d);
        }
    }
}

// ---------------- IMMA int8 tensor-core GEMM --------------------------------
__device__ __forceinline__ void imma16832(int& c0, int& c1, int& c2, int& c3,
                                          int a0, int a1, int a2, int a3,
                                          int b0, int b1) {
    asm volatile(
        "mma.sync.aligned.m16n8k32.row.col.s32.s8.s8.s32 "
        "{%0,%1,%2,%3},{%4,%5,%6,%7},{%8,%9},{%0,%1,%2,%3};"
        : "+r"(c0), "+r"(c1), "+r"(c2), "+r"(c3)
        : "r"(a0), "r"(a1), "r"(a2), "r"(a3), "r"(b0), "r"(b1));
}

__device__ __forceinline__ unsigned out_idx(int m, int n) {
    int bb = m >> 10, s = m & 1023, h = n >> 6, dh = n & 63;
    return (unsigned)(((bb * 16 + h) << 16) + (s << 6) + dh);
}

__device__ __forceinline__ uint32_t smem_u32(const void* p) {
    uint32_t a;
    asm("{ .reg .u64 t; cvta.to.shared.u64 t, %1; cvt.u32.u64 %0, t; }" : "=r"(a) : "l"(p));
    return a;
}

__device__ __forceinline__ void cp16(uint32_t d, const void* s) {
    asm volatile("cp.async.cg.shared.global [%0], [%1], 16;" :: "r"(d), "l"(s));
}

__device__ __forceinline__ unsigned h2w(float x, float y) {
    __half2 h = __float22half2_rn(make_float2(x, y));
    return *(unsigned*)&h;
}

// C[m,n] = sum_d A[m,d]*W[n,d]; 128x128 tile, K=1024 int8 (256 int32/row).
// 256 threads = 8 warps (2m x 4n), warp tile 64x32. cp.async double-buffered.
// Epilogue writes fp16 (paired 4B word stores).
template <int ISV>
__global__ __launch_bounds__(256, ISV ? 1 : 2) void gemm_imma(
    const int* __restrict__ A8, const int* __restrict__ R8,
    const int* __restrict__ wq8, const int* __restrict__ wk8, const int* __restrict__ wv8,
    unsigned short* __restrict__ Qo, unsigned short* __restrict__ Ko,
    unsigned short* __restrict__ Vo)
{
    extern __shared__ int gsm[];   // [2 bufs x 2560] per array: A | B | (R)
    int* AsB = gsm;
    int* BsB = gsm + 5120;
    int* RsB = gsm + 10240;

    int z = ISV ? 2 : blockIdx.z;
    const int* W = (z == 0) ? wq8 : (z == 1) ? wk8 : wv8;

    int tid = threadIdx.x;
    int m0 = blockIdx.y * 128, n0 = blockIdx.x * 128;
    int w = tid >> 5, lane = tid & 31, g = lane >> 2, t = lane & 3;
    int wm = (w >> 2) * 64, wn = (w & 3) * 32;

    int acc1[4][4][4];
    int acc2[ISV ? 4 : 1][ISV ? 4 : 1][4];
#pragma unroll
    for (int mi = 0; mi < 4; mi++)
#pragma unroll
        for (int ni = 0; ni < 4; ni++)
#pragma unroll
            for (int e = 0; e < 4; e++) acc1[mi][ni][e] = 0;
    if (ISV) {
#pragma unroll
        for (int mi = 0; mi < 4; mi++)
#pragma unroll
            for (int ni = 0; ni < 4; ni++)
#pragma unroll
                for (int e = 0; e < 4; e++) acc2[mi][ni][e] = 0;
    }

    int srow = tid >> 1, shalf = (tid & 1) * 8;
    const int* Ag = A8 + (m0 + srow) * 256 + shalf;
    const int* Rg = R8 + (m0 + srow) * 256 + shalf;
    const int* Wg = W  + (n0 + srow) * 256 + shalf;
    int sboff = (srow * 20 + shalf) * 4;

    uint32_t sA = smem_u32(AsB), sB = smem_u32(BsB), sR = smem_u32(RsB);

    {
        cp16(sA + sboff, Ag);      cp16(sA + sboff + 16, Ag + 4);
        cp16(sB + sboff, Wg);      cp16(sB + sboff + 16, Wg + 4);
        if (ISV) { cp16(sR + sboff, Rg); cp16(sR + sboff + 16, Rg + 4); }
        asm volatile("cp.async.commit_group;");
    }

    for (int ks = 0; ks < 16; ks++) {
        int cur = ks & 1, nxt = cur ^ 1;
        if (ks < 15) {
            uint32_t boff = (uint32_t)nxt * 10240u + (uint32_t)sboff;
            const int* a = Ag + (ks + 1) * 16;
            const int* b = Wg + (ks + 1) * 16;
            cp16(sA + boff, a); cp16(sA + boff + 16, a + 4);
            cp16(sB + boff, b); cp16(sB + boff + 16, b + 4);
            if (ISV) {
                const int* r = Rg + (ks + 1) * 16;
                cp16(sR + boff, r); cp16(sR + boff + 16, r + 4);
            }
            asm volatile("cp.async.commit_group;");
            asm volatile("cp.async.wait_group 1;");
        } else {
            asm volatile("cp.async.wait_group 0;");
        }
        __syncthreads();

        const int* Asw = AsB + cur * 2560;
        const int* Bsw = BsB + cur * 2560;
        const int* Rsw = RsB + cur * 2560;

#pragma unroll
        for (int kk = 0; kk < 2; kk++) {
            int bb0[4], bb1[4];
#pragma unroll
            for (int ni = 0; ni < 4; ni++) {
                int brow = (wn + ni * 8 + g) * 20 + kk * 8;
                bb0[ni] = Bsw[brow + t];
                bb1[ni] = Bsw[brow + 4 + t];
            }
#pragma unroll
            for (int mi = 0; mi < 4; mi++) {
                int ar0 = (wm + mi * 16 + g) * 20 + kk * 8;
                int ar1 = (wm + mi * 16 + 8 + g) * 20 + kk * 8;
                int a0 = Asw[ar0 + t], a1 = Asw[ar1 + t];
                int a2 = Asw[ar0 + 4 + t], a3 = Asw[ar1 + 4 + t];
#pragma unroll
                for (int ni = 0; ni < 4; ni++)
                    imma16832(acc1[mi][ni][0], acc1[mi][ni][1], acc1[mi][ni][2], acc1[mi][ni][3],
                              a0, a1, a2, a3, bb0[ni], bb1[ni]);
                if (ISV) {
                    int r0 = Rsw[ar0 + t], r1 = Rsw[ar1 + t];
                    int r2 = Rsw[ar0 + 4 + t], r3 = Rsw[ar1 + 4 + t];
#pragma unroll
                    for (int ni = 0; ni < 4; ni++)
                        imma16832(acc2[mi][ni][0], acc2[mi][ni][1], acc2[mi][ni][2], acc2[mi][ni][3],
                                  r0, r1, r2, r3, bb0[ni], bb1[ni]);
                }
            }
        }
        __syncthreads();
    }

    float sa = fmaxf(__uint_as_float(g_absmax[0]), 1e-8f) / 127.0f;
    float sw = fmaxf(__uint_as_float(g_absmax[z + 1]), 1e-8f) / 7.0f;
    float k1 = sa * sw;
    float k2 = (sa / 254.0f) * sw;
    unsigned short* O = (z == 0) ? Qo : (z == 1) ? Ko : Vo;

#pragma unroll
    for (int mi = 0; mi < 4; mi++) {
        int r0 = m0 + wm + mi * 16 + g;
        int r1 = r0 + 8;
#pragma unroll
        for (int ni = 0; ni < 4; ni++) {
            int c0 = n0 + wn + ni * 8 + 2 * t;
            float v00, v01, v10, v11;
            if (!ISV) {
                v00 = (float)acc1[mi][ni][0] * k1;
                v01 = (float)acc1[mi][ni][1] * k1;
                v10 = (float)acc1[mi][ni][2] * k1;
                v11 = (float)acc1[mi][ni][3] * k1;
            } else {
                v00 = fmaf((float)acc2[mi][ni][0], k2, (float)acc1[mi][ni][0] * k1);
                v01 = fmaf((float)acc2[mi][ni][1], k2, (float)acc1[mi][ni][1] * k1);
                v10 = fmaf((float)acc2[mi][ni][2], k2, (float)acc1[mi][ni][2] * k1);
                v11 = fmaf((float)acc2[mi][ni][3], k2, (float)acc1[mi][ni][3] * k1);
            }
            *(unsigned*)&O[out_idx(r0, c0)] = h2w(v00, v01);
            *(unsigned*)&O[out_idx(r1, c0)] = h2w(v10, v11);
        }
    }
}

// ---------------- JAX threefry2x32 noise (partitionable, key=(0,42)) --------
__device__ __forceinline__ uint32_t rotl32(uint32_t x, int r) {
    return (x << r) | (x >> (32 - r));
}

__device__ __forceinline__ void threefry2x32(uint32_t c0, uint32_t c1,
                                             uint32_t& o0, uint32_t& o1) {
    const uint32_t k0 = 0u, k1 = 42u, k2 = 0u ^ 42u ^ 0x1BD11BDAu;
    uint32_t x0 = c0 + k0, x1 = c1 + k1;
#define TF_R(r) { x0 += x1; x1 = rotl32(x1, r); x1 ^= x0; }
    TF_R(13) TF_R(15) TF_R(26) TF_R(6)
    x0 += k1; x1 += k2 + 1u;
    TF_R(17) TF_R(29) TF_R(16) TF_R(24)
    x0 += k2; x1 += k0 + 2u;
    TF_R(13) TF_R(15) TF_R(26) TF_R(6)
    x0 += k0; x1 += k1 + 3u;
    TF_R(17) TF_R(29) TF_R(16) TF_R(24)
    x0 += k1; x1 += k2 + 4u;
    TF_R(13) TF_R(15) TF_R(26) TF_R(6)
    x0 += k2; x1 += k0 + 5u;
#undef TF_R
    o0 = x0; o1 = x1;
}

__device__ __forceinline__ float noise_at(unsigned int i) {
    uint32_t o0, o1;
    threefry2x32(0u, i, o0, o1);
    uint32_t bits = o0 ^ o1;
    float f = __uint_as_float((bits >> 9) | 0x3f800000u) - 1.0f;
    const float lo = -0.99999994f;
    float u = fmaxf(lo, fmaf(f, 2.0f, lo));
    float t = fmaf(-u, u, 1.0f);
    float w = -__logf(t);
    float p;
    if (w < 5.0f) {
        w = w - 2.5f;
        p = 2.81022636e-08f;
        p = fmaf(p, w, 3.43273939e-07f);
        p = fmaf(p, w, -3.5233877e-06f);
        p = fmaf(p, w, -4.39150654e-06f);
        p = fmaf(p, w, 0.00021858087f);
        p = fmaf(p, w, -0.00125372503f);
        p = fmaf(p, w, -0.00417768164f);
        p = fmaf(p, w, 0.246640727f);
        p = fmaf(p, w, 1.50140941f);
    } else {
        w = sqrtf(w) - 3.0f;
        p = -0.000200214257f;
        p = fmaf(p, w, 0.000100950558f);
        p = fmaf(p, w, 0.00134934322f);
        p = fmaf(p, w, -0.00367342844f);
        p = fmaf(p, w, 0.00573950773f);
        p = fmaf(p, w, -0.0076224613f);
        p = fmaf(p, w, 0.00943887047f);
        p = fmaf(p, w, 1.00167406f);
        p = fmaf(p, w, 2.83297682f);
    }
    return 1.41421356f * (p * u) * 0.05f;
}

// ---------------- HMMA helpers ----------------------------------------------
__device__ __forceinline__ void mma16816(float& c0, float& c1, float& c2, float& c3,
                                         unsigned a0, unsigned a1, unsigned a2, unsigned a3,
                                         unsigned b0, unsigned b1) {
    asm volatile(
        "mma.sync.aligned.m16n8k16.row.col.f32.f16.f16.f32 "
        "{%0,%1,%2,%3},{%4,%5,%6,%7},{%8,%9},{%0,%1,%2,%3};"
        : "+f"(c0), "+f"(c1), "+f"(c2), "+f"(c3)
        : "r"(a0), "r"(a1), "r"(a2), "r"(a3), "r"(b0), "r"(b1));
}

// ---------------- fused flash attention (HMMA, pure fp16 operands) -----------
// Q/K/V fp16; planes as 32-bit words ({d, d+1} half pairs), row stride 36.
// V^T plane [dh][k-pair-word], XOR swizzle col = kp ^ ((dh>>3)&3).
#define PLANEW 2304   // 64 rows * 36 words
__global__ __launch_bounds__(128, 4) void attn_k(
    const unsigned short* __restrict__ Q16, const unsigned short* __restrict__ K16,
    const unsigned short* __restrict__ V16, const float* __restrict__ mask,
    float* __restrict__ out)
{
    extern __shared__ unsigned smw[];
    unsigned* qh_s = smw;
    unsigned* kh_s = smw + PLANEW;
    unsigned* vt_s = smw + 2 * PLANEW;
    float* Ms = (float*)(smw + 3 * PLANEW);

    int bh = blockIdx.x, qt = blockIdx.y;
    int b = bh >> 4, h = bh & 15;
    int tid = threadIdx.x, w = tid >> 5, lane = tid & 31;
    int g = lane >> 2, t = lane & 3;

    // ---- stage Q tile (words = {d,d+1} halves, direct copy)
    const unsigned* Qw = (const unsigned*)(Q16 + (size_t)(bh * 1024 + qt * 64) * 64);
    for (int i = tid; i < 2048; i += 128) {
        int q = i >> 5, dp = i & 31;
        qh_s[q * 36 + dp] = Qw[q * 32 + dp];
    }
    __syncthreads();

    unsigned qh[4][4];
    int qr = w * 16 + g;
#pragma unroll
    for (int c = 0; c < 4; c++) {
        int wp = c * 8 + t;
        qh[c][0] = qh_s[qr * 36 + wp];
        qh[c][1] = qh_s[(qr + 8) * 36 + wp];
        qh[c][2] = qh_s[qr * 36 + wp + 4];
        qh[c][3] = qh_s[(qr + 8) * 36 + wp + 4];
    }

    float m0r = -1e30f, m1r = -1e30f, l0r = 0.f, l1r = 0.f;
    float O[8][4];
#pragma unroll
    for (int n = 0; n < 8; n++)
#pragma unroll
        for (int e = 0; e < 4; e++) O[n][e] = 0.f;

    const float* maskb = mask + (b << 10);
    unsigned base0 = ((unsigned)bh << 20) | ((unsigned)(qt * 64 + qr) << 10);

    for (int kt = 0; kt < 16; kt++) {
        __syncthreads();
        const unsigned* Kw = (const unsigned*)(K16 + (size_t)(bh * 1024 + kt * 64) * 64);
        const unsigned short* Vg = V16 + (size_t)(bh * 1024 + kt * 64) * 64;
        for (int i = tid; i < 2048; i += 128) {
            int k = i >> 5, dp = i & 31;
            kh_s[k * 36 + dp] = Kw[k * 32 + dp];
            int d = i & 63, kp = i >> 6;
            unsigned v0 = Vg[(2 * kp) * 64 + d];
            unsigned v1 = Vg[(2 * kp + 1) * 64 + d];
            int col = kp ^ ((d >> 3) & 3);
            vt_s[d * 36 + col] = v0 | (v1 << 16);
        }
        if (tid < 64) Ms[tid] = maskb[kt * 64 + tid];
        __syncthreads();

        // ---- S = Q K^T (single fp16 term)
        float S[8][4];
#pragma unroll
        for (int n = 0; n < 8; n++)
#pragma unroll
            for (int e = 0; e < 4; e++) S[n][e] = 0.f;

#pragma unroll
        for (int j = 0; j < 8; j++) {
            int krow = j * 8 + g;
#pragma unroll
            for (int c = 0; c < 4; c++) {
                int wp = c * 8 + t;
                unsigned bh0 = kh_s[krow * 36 + wp];
                unsigned bh1 = kh_s[krow * 36 + wp + 4];
                mma16816(S[j][0], S[j][1], S[j][2], S[j][3],
                         qh[c][0], qh[c][1], qh[c][2], qh[c][3], bh0, bh1);
            }
        }

        // ---- scale + noise + mask
#pragma unroll
        for (int j = 0; j < 8; j++) {
            unsigned kc = (unsigned)(kt * 64 + j * 8 + 2 * t);
            float mv0 = Ms[j * 8 + 2 * t], mv1 = Ms[j * 8 + 2 * t + 1];
            S[j][0] = fmaf(S[j][0], 0.125f, noise_at(base0 + kc) + mv0);
            S[j][1] = fmaf(S[j][1], 0.125f, noise_at(base0 + kc + 1) + mv1);
            S[j][2] = fmaf(S[j][2], 0.125f, noise_at(base0 + (8u << 10) + kc) + mv0);
            S[j][3] = fmaf(S[j][3], 0.125f, noise_at(base0 + (8u << 10) + kc + 1) + mv1);
        }

        // ---- online softmax
        float tm0 = -1e30f, tm1 = -1e30f;
#pragma unroll
        for (int j = 0; j < 8; j++) {
            tm0 = fmaxf(tm0, fmaxf(S[j][0], S[j][1]));
            tm1 = fmaxf(tm1, fmaxf(S[j][2], S[j][3]));
        }
        tm0 = fmaxf(tm0, __shfl_xor_sync(0xffffffffu, tm0, 1));
        tm0 = fmaxf(tm0, __shfl_xor_sync(0xffffffffu, tm0, 2));
        tm1 = fmaxf(tm1, __shfl_xor_sync(0xffffffffu, tm1, 1));
        tm1 = fmaxf(tm1, __shfl_xor_sync(0xffffffffu, tm1, 2));
        float mn0 = fmaxf(m0r, tm0), mn1 = fmaxf(m1r, tm1);
        float cor0 = __expf(m0r - mn0), cor1 = __expf(m1r - mn1);
        m0r = mn0; m1r = mn1;
        float ps0 = 0.f, ps1 = 0.f;
#pragma unroll
        for (int j = 0; j < 8; j++) {
            S[j][0] = __expf(S[j][0] - mn0); S[j][1] = __expf(S[j][1] - mn0);
            S[j][2] = __expf(S[j][2] - mn1); S[j][3] = __expf(S[j][3] - mn1);
            ps0 += S[j][0] + S[j][1];
            ps1 += S[j][2] + S[j][3];
        }
        ps0 += __shfl_xor_sync(0xffffffffu, ps0, 1);
        ps0 += __shfl_xor_sync(0xffffffffu, ps0, 2);
        ps1 += __shfl_xor_sync(0xffffffffu, ps1, 1);
        ps1 += __shfl_xor_sync(0xffffffffu, ps1, 2);
        l0r = l0r * cor0 + ps0;
        l1r = l1r * cor1 + ps1;
#pragma unroll
        for (int n = 0; n < 8; n++) {
            O[n][0] *= cor0; O[n][1] *= cor0;
            O[n][2] *= cor1; O[n][3] *= cor1;
        }

        // ---- P -> fp16 A-frags
        unsigned ph[4][4];
#pragma unroll
        for (int c = 0; c < 4; c++) {
            ph[c][0] = h2w(S[2 * c][0],     S[2 * c][1]);
            ph[c][1] = h2w(S[2 * c][2],     S[2 * c][3]);
            ph[c][2] = h2w(S[2 * c + 1][0], S[2 * c + 1][1]);
            ph[c][3] = h2w(S[2 * c + 1][2], S[2 * c + 1][3]);
        }

        // ---- O += P V (single fp16 term; swizzled V^T plane)
#pragma unroll
        for (int n = 0; n < 8; n++) {
            int vrow = n * 8 + g;
            int vs = n & 3;
#pragma unroll
            for (int c = 0; c < 4; c++) {
                int wp0 = (c * 8 + t) ^ vs;
                int wp1 = (c * 8 + 4 + t) ^ vs;
                unsigned bh0 = vt_s[vrow * 36 + wp0];
                unsigned bh1 = vt_s[vrow * 36 + wp1];
                mma16816(O[n][0], O[n][1], O[n][2], O[n][3],
                         ph[c][0], ph[c][1], ph[c][2], ph[c][3], bh0, bh1);
            }
        }
    }

    float inv0 = 1.0f / l0r, inv1 = 1.0f / l1r;
    int q0 = qt * 64 + qr;
    float* o0 = out + ((size_t)((b << 10) + q0)) * 1024 + (h << 6);
    float* o1 = out + ((size_t)((b << 10) + q0 + 8)) * 1024 + (h << 6);
#pragma unroll
    for (int n = 0; n < 8; n++) {
        int dh = n * 8 + 2 * t;
        *(float2*)(o0 + dh) = make_float2(O[n][0] * inv0, O[n][1] * inv0);
        *(float2*)(o1 + dh) = make_float2(O[n][2] * inv1, O[n][3] * inv1);
    }
}

// ---------------- launch -----------------------------------------------------
extern "C" void kernel_launch(void* const* d_in, const int* in_sizes, int n_in,
                              void* d_out, int out_size) {
    const float* hidden = (const float*)d_in[0];
    const float* mask   = (const float*)d_in[1];
    const float* Wq     = (const float*)d_in[2];
    const float* Wk     = (const float*)d_in[3];
    const float* Wv     = (const float*)d_in[4];
    float* out = (float*)d_out;

    int *hq8, *r8, *wq8, *wk8, *wv8;
    unsigned short *Qp, *Kp, *Vp;
    cudaGetSymbolAddress((void**)&hq8, g_hq8);
    cudaGetSymbolAddress((void**)&r8,  g_r8);
    cudaGetSymbolAddress((void**)&wq8, g_wq8);
    cudaGetSymbolAddress((void**)&wk8, g_wk8);
    cudaGetSymbolAddress((void**)&wv8, g_wv8);
    cudaGetSymbolAddress((void**)&Qp,  g_Q16);
    cudaGetSymbolAddress((void**)&Kp,  g_K16);
    cudaGetSymbolAddress((void**)&Vp,  g_V16);

    init_k<<<1, 32>>>();
    absmax_all_k<<<dim3(128, 1, 4), 256>>>((const float4*)hidden, (const float4*)Wq,
                                           (const float4*)Wk, (const float4*)Wv);
    pack_all_k<<<dim3(256, 1, 4), 256>>>((const float4*)hidden, (const float4*)Wq,
                                         (const float4*)Wk, (const float4*)Wv,
                                         hq8, r8, wq8, wk8, wv8);

    cudaFuncSetAttribute(gemm_imma<0>, cudaFuncAttributeMaxDynamicSharedMemorySize, 40960);
    cudaFuncSetAttribute(gemm_imma<1>, cudaFuncAttributeMaxDynamicSharedMemorySize, 61440);
    gemm_imma<0><<<dim3(8, 32, 2), 256, 40960>>>(hq8, r8, wq8, wk8, wv8, Qp, Kp, Vp);
    gemm_imma<1><<<dim3(8, 32, 1), 256, 61440>>>(hq8, r8, wq8, wk8, wv8, Qp, Kp, Vp);

    int smem_bytes = 3 * PLANEW * 4 + 64 * 4;
    cudaFuncSetAttribute(attn_k, cudaFuncAttributeMaxDynamicSharedMemorySize, smem_bytes);
    attn_k<<<dim3(64, 16), 128, smem_bytes>>>(Qp, Kp, Vp, mask, out);
}